// round 1
// baseline (speedup 1.0000x reference)
#include <cuda_runtime.h>
#include <stdint.h>

#define NPRED    25200
#define PRED_C   9
#define TOPK     1000
#define SORTN    8192          // power-of-two candidate capacity (~2500 expected)
#define NTHREADS 1024
#define CONF_T   0.7f
#define IOU_T    0.45f
#define MASKW    32            // 32 u32 words cover 1000 (<=1024) columns

struct SMem {
    union {
        unsigned long long skey[SORTN];      // 64 KB  (phase A: sort keys)
        unsigned int       mask[TOPK * MASKW]; // 128 KB (phase B: suppression bitmask)
    } u;
    float4       sbox [TOPK];   // xyxy boxes of top-1000
    float        sarea[TOPK];
    float        sscore[TOPK];
    int          sidx [TOPK];   // original prediction row (-1 if pad)
    unsigned int skeepw[MASKW]; // final removal bitmask
    int          scount;
};

__global__ __launch_bounds__(NTHREADS, 1)
void nms_kernel(const float* __restrict__ pred,
                float* __restrict__ out,        // [B, TOPK, 9]
                float* __restrict__ keep_out)   // [B, TOPK] as 0/1 f32
{
    extern __shared__ unsigned char smem_raw[];
    SMem* s = reinterpret_cast<SMem*>(smem_raw);

    const int img = blockIdx.x;
    const int tid = threadIdx.x;
    const float* p = pred + (size_t)img * NPRED * PRED_C;

    if (tid == 0) s->scount = 0;
    __syncthreads();

    // ---- Phase A: filter candidates (conf = obj*cls, both > 0.7) ----
    for (int i = tid; i < NPRED; i += NTHREADS) {
        float obj = p[i * PRED_C + 4];
        float cls = p[i * PRED_C + 5];
        float conf = __fmul_rn(obj, cls);
        if (obj > CONF_T && conf > CONF_T) {
            int pos = atomicAdd(&s->scount, 1);
            if (pos < SORTN) {
                // key: conf bits (positive floats sort like uints) high,
                // ~index low so ties pick the SMALLER index first (jax top_k stable)
                unsigned long long key =
                    ((unsigned long long)__float_as_uint(conf) << 32) |
                    (unsigned long long)(0xFFFFFFFFu - (unsigned)i);
                s->u.skey[pos] = key;
            }
        }
    }
    __syncthreads();

    int M = s->scount;
    if (M > SORTN) M = SORTN;
    for (int i = M + tid; i < SORTN; i += NTHREADS) s->u.skey[i] = 0ull;
    __syncthreads();

    // ---- Phase A2: bitonic sort DESCENDING over SORTN u64 keys ----
    for (int k = 2; k <= SORTN; k <<= 1) {
        for (int j = k >> 1; j > 0; j >>= 1) {
            #pragma unroll
            for (int q = 0; q < SORTN / NTHREADS; q++) {
                int i = tid + q * NTHREADS;
                int ixj = i ^ j;
                if (ixj > i) {
                    unsigned long long a = s->u.skey[i];
                    unsigned long long b = s->u.skey[ixj];
                    bool descSeg = ((i & k) == 0);
                    if (descSeg ? (a < b) : (a > b)) {
                        s->u.skey[i]   = b;
                        s->u.skey[ixj] = a;
                    }
                }
            }
            __syncthreads();
        }
    }

    // ---- Phase A3: extract top-1000 -> boxes/areas/scores (before union reuse) ----
    if (tid < TOPK) {
        unsigned long long key = s->u.skey[tid];
        float4 b;
        float sc, ar;
        int idx;
        if ((key >> 32) != 0ull) {
            idx = (int)(0xFFFFFFFFu - (unsigned)(key & 0xFFFFFFFFull));
            sc = __uint_as_float((unsigned)(key >> 32));
            float x = p[idx * PRED_C + 0];
            float y = p[idx * PRED_C + 1];
            float w = p[idx * PRED_C + 2];
            float h = p[idx * PRED_C + 3];
            float hw = __fmul_rn(w, 0.5f);
            float hh = __fmul_rn(h, 0.5f);
            b.x = __fsub_rn(x, hw);
            b.y = __fsub_rn(y, hh);
            b.z = __fadd_rn(x, hw);
            b.w = __fadd_rn(y, hh);
            ar = __fmul_rn(__fsub_rn(b.z, b.x), __fsub_rn(b.w, b.y));
        } else {
            idx = -1; sc = -1.0f; ar = 0.0f;
            b.x = b.y = b.z = b.w = 0.0f;
        }
        s->sbox[tid] = b;
        s->sarea[tid] = ar;
        s->sscore[tid] = sc;
        s->sidx[tid] = idx;
    }
    __syncthreads();

    // ---- Phase B1: 1000x1000 IoU suppression bitmask (j > i only) ----
    for (int pidx = tid; pidx < TOPK * MASKW; pidx += NTHREADS) {
        int i = pidx >> 5;        // row
        int w = pidx & 31;        // word
        float4 bi = s->sbox[i];
        float  ai = s->sarea[i];
        unsigned int m = 0;
        int jbase = w << 5;
        #pragma unroll 8
        for (int bb = 0; bb < 32; bb++) {
            int j = jbase + bb;
            if (j > i && j < TOPK) {
                float4 bj = s->sbox[j];
                float lx = fmaxf(bi.x, bj.x);
                float ly = fmaxf(bi.y, bj.y);
                float rx = fminf(bi.z, bj.z);
                float ry = fminf(bi.w, bj.w);
                float iw = fmaxf(__fsub_rn(rx, lx), 0.0f);
                float ih = fmaxf(__fsub_rn(ry, ly), 0.0f);
                float inter = __fmul_rn(iw, ih);
                // reference order: ((ai + aj) - inter) + 1e-7
                float denom = __fadd_rn(__fsub_rn(__fadd_rn(ai, s->sarea[j]), inter), 1e-7f);
                float iou = __fdiv_rn(inter, denom);
                if (iou > IOU_T) m |= (1u << bb);
            }
        }
        s->u.mask[pidx] = m;
    }
    __syncthreads();

    // ---- Phase B2: serial greedy sweep (warp 0; lane l owns removal word l) ----
    if (tid < 32) {
        unsigned int remv = 0;
        for (int i = 0; i < TOPK; i++) {
            int wi = i >> 5;
            int alive = 0;
            if (tid == wi) {
                alive = (((remv >> (i & 31)) & 1u) == 0u) && (s->sscore[i] > CONF_T);
            }
            alive = __shfl_sync(0xFFFFFFFFu, alive, wi);
            if (alive) remv |= s->u.mask[i * MASKW + tid];
        }
        s->skeepw[tid] = remv;
    }
    __syncthreads();

    // ---- Phase C: write out (zeros where not kept) + keep mask ----
    if (tid < TOPK) {
        int i = tid;
        bool removed = (s->skeepw[i >> 5] >> (i & 31)) & 1u;
        bool kp = (s->sscore[i] > CONF_T) && !removed;
        float o0 = 0.f, o1 = 0.f, o2 = 0.f, o3 = 0.f, o4 = 0.f;
        float o6 = 0.f, o7 = 0.f, o8 = 0.f;
        if (kp) {
            float4 b = s->sbox[i];
            o0 = b.x; o1 = b.y; o2 = b.z; o3 = b.w;
            o4 = s->sscore[i];
            int idx = s->sidx[i];
            o6 = p[idx * PRED_C + 6];
            o7 = p[idx * PRED_C + 7];
            o8 = p[idx * PRED_C + 8];
        }
        float* orow = out + ((size_t)img * TOPK + i) * PRED_C;
        orow[0] = o0; orow[1] = o1; orow[2] = o2; orow[3] = o3;
        orow[4] = o4; orow[5] = 0.0f;
        orow[6] = o6; orow[7] = o7; orow[8] = o8;
        keep_out[(size_t)img * TOPK + i] = kp ? 1.0f : 0.0f;
    }
}

extern "C" void kernel_launch(void* const* d_in, const int* in_sizes, int n_in,
                              void* d_out, int out_size)
{
    const float* pred = (const float*)d_in[0];
    int B = in_sizes[0] / (NPRED * PRED_C);

    float* out = (float*)d_out;                       // [B, TOPK, 9]
    float* keep = out + (size_t)B * TOPK * PRED_C;    // [B, TOPK]

    size_t smem = sizeof(SMem);
    cudaFuncSetAttribute(nms_kernel,
                         cudaFuncAttributeMaxDynamicSharedMemorySize, (int)smem);
    nms_kernel<<<B, NTHREADS, smem>>>(pred, out, keep);
}

// round 2
// speedup vs baseline: 3.6213x; 3.6213x over previous
#include <cuda_runtime.h>
#include <stdint.h>

#define NPRED    25200
#define PRED_C   9
#define TOPK     1000
#define SORTN    4096          // candidate capacity (expected ~2535, sigma ~48)
#define NTHREADS 1024
#define CONF_T   0.7f
#define IOU_T    0.45f
#define MASKW    32
#define BMAX     32
#define SLICES   8
#define ROWS_PER (TOPK / SLICES)   // 125

// ---- global scratch (no allocations allowed) ----
__device__ float4       g_box  [BMAX * 1024];
__device__ float        g_score[BMAX * 1024];
__device__ int          g_idx  [BMAX * 1024];
__device__ unsigned int g_mask [BMAX * TOPK * MASKW];   // 4 MB

// ============================================================
// Kernel A: filter + bitonic top-k  (one CTA per image)
// ============================================================
__global__ __launch_bounds__(NTHREADS, 1)
void k_topk(const float* __restrict__ pred)
{
    __shared__ unsigned long long skey[SORTN];
    __shared__ int scount;

    const int img = blockIdx.x;
    const int tid = threadIdx.x;
    const float* p = pred + (size_t)img * NPRED * PRED_C;

    if (tid == 0) scount = 0;
    __syncthreads();

    for (int i = tid; i < NPRED; i += NTHREADS) {
        float obj = p[i * PRED_C + 4];
        float cls = p[i * PRED_C + 5];
        float conf = __fmul_rn(obj, cls);
        if (obj > CONF_T && conf > CONF_T) {
            int pos = atomicAdd(&scount, 1);
            if (pos < SORTN) {
                // conf bits high; ~index low => ties pick smaller index first
                skey[pos] = ((unsigned long long)__float_as_uint(conf) << 32) |
                            (unsigned long long)(0xFFFFFFFFu - (unsigned)i);
            }
        }
    }
    __syncthreads();

    int M = scount; if (M > SORTN) M = SORTN;
    for (int i = M + tid; i < SORTN; i += NTHREADS) skey[i] = 0ull;
    __syncthreads();

    // bitonic sort descending
    for (int k = 2; k <= SORTN; k <<= 1) {
        for (int j = k >> 1; j > 0; j >>= 1) {
            #pragma unroll
            for (int q = 0; q < SORTN / NTHREADS; q++) {
                int i = tid + q * NTHREADS;
                int ixj = i ^ j;
                if (ixj > i) {
                    unsigned long long a = skey[i];
                    unsigned long long b = skey[ixj];
                    if (((i & k) == 0) ? (a < b) : (a > b)) {
                        skey[i] = b; skey[ixj] = a;
                    }
                }
            }
            __syncthreads();
        }
    }

    if (tid < TOPK) {
        unsigned long long key = skey[tid];
        float4 b; float sc; int idx;
        if ((key >> 32) != 0ull) {
            idx = (int)(0xFFFFFFFFu - (unsigned)(key & 0xFFFFFFFFull));
            sc  = __uint_as_float((unsigned)(key >> 32));
            float x = p[idx * PRED_C + 0];
            float y = p[idx * PRED_C + 1];
            float w = p[idx * PRED_C + 2];
            float h = p[idx * PRED_C + 3];
            float hw = __fmul_rn(w, 0.5f);
            float hh = __fmul_rn(h, 0.5f);
            b = make_float4(__fsub_rn(x, hw), __fsub_rn(y, hh),
                            __fadd_rn(x, hw), __fadd_rn(y, hh));
        } else {
            idx = -1; sc = -1.0f; b = make_float4(0.f, 0.f, 0.f, 0.f);
        }
        g_box  [img * 1024 + tid] = b;
        g_score[img * 1024 + tid] = sc;
        g_idx  [img * 1024 + tid] = idx;
    }
}

// ============================================================
// Kernel B: IoU suppression bitmask (grid = 32 x SLICES CTAs)
// Warp w owns column block j in [32w, 32w+32); its 32 bj boxes
// are loaded once. Per row: broadcast bi + 1 IoU/lane + ballot.
// ============================================================
__global__ __launch_bounds__(NTHREADS, 1)
void k_mask()
{
    __shared__ float4 sbox[TOPK];

    const int img   = blockIdx.x;
    const int slice = blockIdx.y;
    const int tid   = threadIdx.x;
    const int warp  = tid >> 5;
    const int lane  = tid & 31;

    for (int i = tid; i < TOPK; i += NTHREADS)
        sbox[i] = g_box[img * 1024 + i];
    __syncthreads();

    unsigned int* gm = g_mask + (size_t)img * TOPK * MASKW;

    const int w = warp;                 // fixed word per warp
    const int j = w * 32 + lane;
    const bool jvalid = (j < TOPK);
    float4 bj = sbox[jvalid ? j : 0];
    float  aj = __fmul_rn(__fsub_rn(bj.z, bj.x), __fsub_rn(bj.w, bj.y));

    const int row0 = slice * ROWS_PER;
    const int jmax = w * 32 + 31;

    for (int r = 0; r < ROWS_PER; r++) {
        int i = row0 + r;
        unsigned int word = 0;
        if (jmax > i) {                 // word intersects upper triangle
            float4 bi = sbox[i];        // broadcast
            float  ai = __fmul_rn(__fsub_rn(bi.z, bi.x), __fsub_rn(bi.w, bi.y));
            bool sup = false;
            if (j > i && jvalid) {
                float lx = fmaxf(bi.x, bj.x);
                float ly = fmaxf(bi.y, bj.y);
                float rx = fminf(bi.z, bj.z);
                float ry = fminf(bi.w, bj.w);
                float iw = fmaxf(__fsub_rn(rx, lx), 0.0f);
                float ih = fmaxf(__fsub_rn(ry, ly), 0.0f);
                float inter = __fmul_rn(iw, ih);
                float denom = __fadd_rn(__fsub_rn(__fadd_rn(ai, aj), inter), 1e-7f);
                sup = (__fdiv_rn(inter, denom) > IOU_T);
            }
            word = __ballot_sync(0xFFFFFFFFu, sup);
        }
        if (lane == 0) gm[i * MASKW + w] = word;
    }
}

// ============================================================
// Kernel C: greedy sweep (chunked, warp 0) + output write
// ============================================================
__global__ __launch_bounds__(NTHREADS, 1)
void k_sweep(const float* __restrict__ pred,
             float* __restrict__ out,
             float* __restrict__ keep_out)
{
    extern __shared__ unsigned char smem_raw[];
    unsigned int* smask  = (unsigned int*)smem_raw;                    // TOPK*32
    float*        sscore = (float*)(smask + TOPK * MASKW);             // TOPK
    unsigned int* sremv  = (unsigned int*)(sscore + TOPK);             // 32

    const int img = blockIdx.x;
    const int tid = threadIdx.x;

    const unsigned int* gm = g_mask + (size_t)img * TOPK * MASKW;
    for (int i = tid; i < TOPK * MASKW; i += NTHREADS) smask[i] = gm[i];
    for (int i = tid; i < TOPK; i += NTHREADS) sscore[i] = g_score[img * 1024 + i];
    __syncthreads();

    if (tid < 32) {
        unsigned int remv = 0;                 // lane owns removal word `tid`
        for (int w = 0; w < 32; w++) {
            int base = w * 32;
            int nb = TOPK - base; if (nb > 32) nb = 32;
            if (nb <= 0) break;
            unsigned int cur = __shfl_sync(0xFFFFFFFFu, remv, w);
            for (int b = 0; b < nb; b++) {
                int i = base + b;
                bool alive = !((cur >> b) & 1u) && (sscore[i] > CONF_T);
                if (alive) {                       // warp-uniform branch
                    remv |= smask[i * MASKW + tid];
                    cur  |= smask[i * MASKW + w];  // broadcast
                }
            }
        }
        sremv[tid] = remv;
    }
    __syncthreads();

    const float* p = pred + (size_t)img * NPRED * PRED_C;
    if (tid < TOPK) {
        int i = tid;
        bool removed = (sremv[i >> 5] >> (i & 31)) & 1u;
        float sc = sscore[i];
        bool kp = (sc > CONF_T) && !removed;
        float o0=0.f,o1=0.f,o2=0.f,o3=0.f,o4=0.f,o6=0.f,o7=0.f,o8=0.f;
        if (kp) {
            float4 b = g_box[img * 1024 + i];
            o0 = b.x; o1 = b.y; o2 = b.z; o3 = b.w;
            o4 = sc;
            int idx = g_idx[img * 1024 + i];
            o6 = p[idx * PRED_C + 6];
            o7 = p[idx * PRED_C + 7];
            o8 = p[idx * PRED_C + 8];
        }
        float* orow = out + ((size_t)img * TOPK + i) * PRED_C;
        orow[0]=o0; orow[1]=o1; orow[2]=o2; orow[3]=o3;
        orow[4]=o4; orow[5]=0.0f;
        orow[6]=o6; orow[7]=o7; orow[8]=o8;
        keep_out[(size_t)img * TOPK + i] = kp ? 1.0f : 0.0f;
    }
}

extern "C" void kernel_launch(void* const* d_in, const int* in_sizes, int n_in,
                              void* d_out, int out_size)
{
    const float* pred = (const float*)d_in[0];
    int B = in_sizes[0] / (NPRED * PRED_C);

    float* out  = (float*)d_out;                      // [B, TOPK, 9]
    float* keep = out + (size_t)B * TOPK * PRED_C;    // [B, TOPK]

    size_t smemC = (size_t)TOPK * MASKW * 4 + TOPK * 4 + 32 * 4;
    static bool attr_set = false;
    if (!attr_set) {
        cudaFuncSetAttribute(k_sweep, cudaFuncAttributeMaxDynamicSharedMemorySize,
                             (int)smemC);
        attr_set = true;
    }

    k_topk<<<B, NTHREADS>>>(pred);
    k_mask<<<dim3(B, SLICES), NTHREADS>>>();
    k_sweep<<<B, NTHREADS, smemC>>>(pred, out, keep);
}

// round 3
// speedup vs baseline: 4.8279x; 1.3332x over previous
#include <cuda_runtime.h>
#include <stdint.h>

#define NPRED    25200
#define PRED_C   9
#define TOPK     1000
#define CONF_T   0.7f
#define IOU_T    0.45f
#define MASKW    32
#define BMAX     32

#define NSLICE   25
#define ROWS_SL  1008          // 25200 / 25
#define FILT_T   256

#define CANDCAP  4096
#define SEL_N    2048          // normal sort size after histogram selection
#define SORT_T   1024

#define MSLICES  8
#define MASK_T   256
#define NWARP_G  (MSLICES * (MASK_T/32))   // 64 warps per image
#define TASKS    16872         // sum_w min(1000, 32w+32)

typedef unsigned long long u64;
typedef unsigned int u32;

// ---------------- global scratch ----------------
__device__ int    g_cnt [BMAX * NSLICE];
__device__ u64    g_cand[BMAX * NSLICE * ROWS_SL];
__device__ float4 g_box [BMAX * 1024];
__device__ float  g_score[BMAX * 1024];
__device__ float  g_area[BMAX * 1024];
__device__ int    g_idx [BMAX * 1024];
__device__ u32    g_mask[BMAX * TOPK * MASKW];   // lower-triangle words never written (stay 0)

// ============================================================
// 1) filter: full-chip pass over predictions
// ============================================================
__global__ __launch_bounds__(FILT_T)
void k_filter(const float* __restrict__ pred)
{
    __shared__ u64 buf[ROWS_SL];
    __shared__ int cnt;

    const int img   = blockIdx.x;
    const int slice = blockIdx.y;
    const int tid   = threadIdx.x;
    const float* p  = pred + (size_t)img * NPRED * PRED_C;

    if (tid == 0) cnt = 0;
    __syncthreads();

    const int base = slice * ROWS_SL;
    #pragma unroll
    for (int r = 0; r < 4; r++) {
        int row = tid + r * FILT_T;
        if (row < ROWS_SL) {
            int i = base + row;
            float obj = p[i * PRED_C + 4];
            float cls = p[i * PRED_C + 5];
            float conf = __fmul_rn(obj, cls);
            if (obj > CONF_T && conf > CONF_T) {
                int pos = atomicAdd(&cnt, 1);
                buf[pos] = ((u64)__float_as_uint(conf) << 32) |
                           (u64)(0xFFFFFFFFu - (u32)i);
            }
        }
    }
    __syncthreads();

    int n = cnt;
    if (tid == 0) g_cnt[img * NSLICE + slice] = n;
    u64* dst = g_cand + (size_t)(img * NSLICE + slice) * ROWS_SL;
    for (int k = tid; k < n; k += FILT_T) dst[k] = buf[k];
}

// ============================================================
// 2) sort: gather candidates, histogram-select ~top-1000, bitonic
// ============================================================
__global__ __launch_bounds__(SORT_T, 1)
void k_sort(const float* __restrict__ pred)
{
    extern __shared__ unsigned char sraw[];
    u64* skey  = (u64*)sraw;                          // 4096
    u64* skey2 = skey + CANDCAP;                      // 2048
    u32* hist  = (u32*)(skey2 + SEL_N);               // 1024
    u32* hist2 = hist + 1024;                         // 1024
    int* spfx  = (int*)(hist2 + 1024);                // 26
    int* misc  = spfx + 32;                           // [0]=total [1]=T [2]=kept

    const int img = blockIdx.x;
    const int tid = threadIdx.x;
    const float* p = pred + (size_t)img * NPRED * PRED_C;

    // prefix over slice counts (warp 0)
    if (tid < 32) {
        int c = (tid < NSLICE) ? g_cnt[img * NSLICE + tid] : 0;
        int x = c;
        #pragma unroll
        for (int d = 1; d < 32; d <<= 1) {
            int y = __shfl_up_sync(0xFFFFFFFFu, x, d);
            if ((tid & 31) >= d) x += y;
        }
        spfx[tid + 1] = x;           // inclusive
        if (tid == 0) spfx[0] = 0;
        if (tid == 31) misc[0] = x;  // total (NSLICE<=32 so lane31 has full sum)
    }
    __syncthreads();

    int total = misc[0];
    if (total > CANDCAP) total = CANDCAP;

    // gather candidate keys
    for (int s = 0; s < NSLICE; s++) {
        int b0 = spfx[s], b1 = spfx[s + 1];
        const u64* src = g_cand + (size_t)(img * NSLICE + s) * ROWS_SL;
        for (int k = b0 + tid; k < b1; k += SORT_T)
            if (k < CANDCAP) skey[k] = src[k - b0];
    }
    for (int k = total + tid; k < CANDCAP; k += SORT_T) skey[k] = 0ull;
    if (tid < 1024) { hist[tid] = 0; }
    __syncthreads();

    // histogram of conf bits (monotonic bins)
    for (int k = tid; k < total; k += SORT_T) {
        u32 bits = (u32)(skey[k] >> 32);
        int b = (int)((bits - 0x3F000000u) >> 13);
        b = b < 0 ? 0 : (b > 1023 ? 1023 : b);
        atomicAdd(&hist[b], 1u);
    }
    __syncthreads();

    // suffix sums (Hillis-Steele, ping-pong)
    u32 *ha = hist, *hb = hist2;
    for (int d = 1; d < 1024; d <<= 1) {
        u32 v = ha[tid] + ((tid + d < 1024) ? ha[tid + d] : 0u);
        hb[tid] = v;
        __syncthreads();
        u32* t = ha; ha = hb; hb = t;
    }
    // ha[b] = #items with bin >= b
    int need = total < TOPK ? total : TOPK;
    if ((int)ha[tid] >= need && (tid == 1023 || (int)ha[tid + 1] < need))
        misc[1] = tid;
    if (tid == 0) misc[2] = 0;
    __syncthreads();

    int T = misc[1];
    int kept = (int)ha[T];
    bool fallback = (kept > SEL_N);

    u64* sbuf; int n;
    if (!fallback) {
        for (int k = tid; k < total; k += SORT_T) {
            u64 key = skey[k];
            u32 bits = (u32)(key >> 32);
            int b = (int)((bits - 0x3F000000u) >> 13);
            b = b < 0 ? 0 : (b > 1023 ? 1023 : b);
            if (b >= T) {
                int pos = atomicAdd(&misc[2], 1);
                skey2[pos] = key;
            }
        }
        __syncthreads();
        for (int k = kept + tid; k < SEL_N; k += SORT_T) skey2[k] = 0ull;
        sbuf = skey2; n = SEL_N;
    } else {
        sbuf = skey; n = CANDCAP;
    }
    __syncthreads();

    // bitonic sort descending
    for (int k = 2; k <= n; k <<= 1) {
        for (int j = k >> 1; j > 0; j >>= 1) {
            for (int q = 0; q < n; q += SORT_T) {
                int i = tid + q;
                int ixj = i ^ j;
                if (ixj > i) {
                    u64 a = sbuf[i], b = sbuf[ixj];
                    if (((i & k) == 0) ? (a < b) : (a > b)) {
                        sbuf[i] = b; sbuf[ixj] = a;
                    }
                }
            }
            __syncthreads();
        }
    }

    // extract top-1000
    if (tid < TOPK) {
        u64 key = sbuf[tid];
        float4 b; float sc, ar; int idx;
        if ((key >> 32) != 0ull) {
            idx = (int)(0xFFFFFFFFu - (u32)(key & 0xFFFFFFFFull));
            sc  = __uint_as_float((u32)(key >> 32));
            float x = p[idx * PRED_C + 0];
            float y = p[idx * PRED_C + 1];
            float w = p[idx * PRED_C + 2];
            float h = p[idx * PRED_C + 3];
            float hw = __fmul_rn(w, 0.5f);
            float hh = __fmul_rn(h, 0.5f);
            b = make_float4(__fsub_rn(x, hw), __fsub_rn(y, hh),
                            __fadd_rn(x, hw), __fadd_rn(y, hh));
            ar = __fmul_rn(__fsub_rn(b.z, b.x), __fsub_rn(b.w, b.y));
        } else {
            idx = -1; sc = -1.0f; ar = 0.0f;
            b = make_float4(0.f, 0.f, 0.f, 0.f);
        }
        g_box  [img * 1024 + tid] = b;
        g_score[img * 1024 + tid] = sc;
        g_area [img * 1024 + tid] = ar;
        g_idx  [img * 1024 + tid] = idx;
    }
}

// ============================================================
// 3) mask: balanced upper-triangle (row, word) tasks, ballot per word
// ============================================================
__global__ __launch_bounds__(MASK_T)
void k_mask()
{
    __shared__ float4 sbox[TOPK];
    __shared__ float  sarea[TOPK];

    const int img  = blockIdx.x;
    const int tid  = threadIdx.x;
    const int lane = tid & 31;
    const int gw   = blockIdx.y * (MASK_T / 32) + (tid >> 5);  // 0..63

    for (int i = tid; i < TOPK; i += MASK_T) {
        sbox[i]  = g_box [img * 1024 + i];
        sarea[i] = g_area[img * 1024 + i];
    }
    __syncthreads();

    u32* gm = g_mask + (size_t)img * TOPK * MASKW;

    int u    = (int)(((long long)gw * TASKS) >> 6);       // /64
    int uend = (int)(((long long)(gw + 1) * TASKS) >> 6);

    // locate (w, i) for task u
    int w = 0, acc = 0;
    while (true) {
        int cw = 32 * w + 32; if (cw > TOPK) cw = TOPK;
        if (acc + cw > u) break;
        acc += cw; w++;
    }
    int i  = u - acc;
    int cw = 32 * w + 32; if (cw > TOPK) cw = TOPK;

    int j = w * 32 + lane;
    bool jv = (j < TOPK);
    float4 bj = sbox[jv ? j : 0];
    float  aj = sarea[jv ? j : 0];

    for (; u < uend; ++u) {
        if (i == cw) {
            w++; i = 0;
            cw = 32 * w + 32; if (cw > TOPK) cw = TOPK;
            j = w * 32 + lane;
            jv = (j < TOPK);
            bj = sbox[jv ? j : 0];
            aj = sarea[jv ? j : 0];
        }
        float4 bi = sbox[i];          // broadcast
        float  ai = sarea[i];
        float lx = fmaxf(bi.x, bj.x);
        float ly = fmaxf(bi.y, bj.y);
        float rx = fminf(bi.z, bj.z);
        float ry = fminf(bi.w, bj.w);
        float iw = fmaxf(__fsub_rn(rx, lx), 0.0f);
        float ih = fmaxf(__fsub_rn(ry, ly), 0.0f);
        float inter = __fmul_rn(iw, ih);
        bool sup = false;
        if (j > i && jv && inter > 0.0f) {   // iou==0 can never exceed 0.45
            float denom = __fadd_rn(__fsub_rn(__fadd_rn(ai, aj), inter), 1e-7f);
            sup = (__fdiv_rn(inter, denom) > IOU_T);
        }
        u32 word = __ballot_sync(0xFFFFFFFFu, sup);
        if (lane == 0) gm[i * MASKW + w] = word;
        i++;
    }
}

// ============================================================
// 4) sweep: ffs-skip serial greedy + outputs
// ============================================================
__global__ __launch_bounds__(SORT_T, 1)
void k_sweep(const float* __restrict__ pred,
             float* __restrict__ out,
             float* __restrict__ keep_out)
{
    extern __shared__ unsigned char sraw[];
    u32* smask  = (u32*)sraw;                 // TOPK*32
    u32* svalid = smask + TOPK * MASKW;       // 32
    u32* sremv  = svalid + 32;                // 32

    const int img = blockIdx.x;
    const int tid = threadIdx.x;
    const int warp = tid >> 5, lane = tid & 31;

    // mask fill (L2-resident), vectorized
    {
        const uint4* src = (const uint4*)(g_mask + (size_t)img * TOPK * MASKW);
        uint4* dst = (uint4*)smask;
        for (int k = tid; k < TOPK * MASKW / 4; k += SORT_T) dst[k] = src[k];
    }

    // score per thread + per-chunk validity words
    float sc = (tid < TOPK) ? g_score[img * 1024 + tid] : -1.0f;
    u32 vb = __ballot_sync(0xFFFFFFFFu, sc > CONF_T);
    if (lane == 0) svalid[warp] = vb;
    __syncthreads();

    if (tid < 32) {
        u32 remv = 0;                      // lane owns removal word `tid`
        for (int w = 0; w < 32; w++) {
            u32 cur = __shfl_sync(0xFFFFFFFFu, remv, w);
            u32 m = svalid[w] & ~cur;
            while (m) {
                int b = __ffs(m) - 1;
                m &= m - 1;
                int i = w * 32 + b;
                u32 v = smask[i * MASKW + tid];
                remv |= v;
                u32 supw = __shfl_sync(0xFFFFFFFFu, v, w);
                m &= ~supw;
            }
        }
        sremv[tid] = remv;
    }
    __syncthreads();

    const float* p = pred + (size_t)img * NPRED * PRED_C;
    if (tid < TOPK) {
        bool removed = (sremv[tid >> 5] >> (tid & 31)) & 1u;
        bool kp = (sc > CONF_T) && !removed;
        float o0=0.f,o1=0.f,o2=0.f,o3=0.f,o4=0.f,o6=0.f,o7=0.f,o8=0.f;
        if (kp) {
            float4 b = g_box[img * 1024 + tid];
            o0 = b.x; o1 = b.y; o2 = b.z; o3 = b.w;
            o4 = sc;
            int idx = g_idx[img * 1024 + tid];
            o6 = p[idx * PRED_C + 6];
            o7 = p[idx * PRED_C + 7];
            o8 = p[idx * PRED_C + 8];
        }
        float* orow = out + ((size_t)img * TOPK + tid) * PRED_C;
        orow[0]=o0; orow[1]=o1; orow[2]=o2; orow[3]=o3;
        orow[4]=o4; orow[5]=0.0f;
        orow[6]=o6; orow[7]=o7; orow[8]=o8;
        keep_out[(size_t)img * TOPK + tid] = kp ? 1.0f : 0.0f;
    }
}

extern "C" void kernel_launch(void* const* d_in, const int* in_sizes, int n_in,
                              void* d_out, int out_size)
{
    const float* pred = (const float*)d_in[0];
    int B = in_sizes[0] / (NPRED * PRED_C);

    float* out  = (float*)d_out;
    float* keep = out + (size_t)B * TOPK * PRED_C;

    size_t smemSort  = (size_t)CANDCAP * 8 + SEL_N * 8 + 1024 * 4 * 2 + 64 * 4;
    size_t smemSweep = (size_t)TOPK * MASKW * 4 + 64 * 4;

    static bool attr_set = false;
    if (!attr_set) {
        cudaFuncSetAttribute(k_sort,  cudaFuncAttributeMaxDynamicSharedMemorySize,
                             (int)smemSort);
        cudaFuncSetAttribute(k_sweep, cudaFuncAttributeMaxDynamicSharedMemorySize,
                             (int)smemSweep);
        attr_set = true;
    }

    k_filter<<<dim3(B, NSLICE), FILT_T>>>(pred);
    k_sort<<<B, SORT_T, smemSort>>>(pred);
    k_mask<<<dim3(B, MSLICES), MASK_T>>>();
    k_sweep<<<B, SORT_T, smemSweep>>>(pred, out, keep);
}

// round 4
// speedup vs baseline: 6.0263x; 1.2482x over previous
#include <cuda_runtime.h>
#include <stdint.h>

#define NPRED    25200
#define PRED_C   9
#define TOPK     1000
#define CONF_T   0.7f
#define IOU_T    0.45f
#define MASKW    32
#define BMAX     32

#define NSLICE   25
#define ROWS_SL  1008
#define FILT_T   256

#define CANDCAP  4096
#define SEL_N    1024
#define SORT_T   1024

#define MSLICES  16
#define MASK_T   256
#define NWARPS_M (MSLICES * (MASK_T / 32))    // 128 warps per image
#define TASKS    16872                        // sum_w min(1000, 32w+32)

#define SWEEP_T  256

typedef unsigned long long u64;
typedef unsigned int u32;

// ---------------- global scratch ----------------
__device__ int    g_cnt [BMAX * NSLICE];
__device__ u64    g_cand[BMAX * NSLICE * ROWS_SL];
__device__ float4 g_box [BMAX * 1024];
__device__ float  g_score[BMAX * 1024];
__device__ float  g_area[BMAX * 1024];
__device__ int    g_idx [BMAX * 1024];
__device__ u32    g_mask[BMAX * TOPK * MASKW];   // lower-triangle words never written (stay 0)

// ============================================================
// 1) filter: full-chip pass over predictions
// ============================================================
__global__ __launch_bounds__(FILT_T)
void k_filter(const float* __restrict__ pred)
{
    __shared__ u64 buf[ROWS_SL];
    __shared__ int cnt;

    const int img   = blockIdx.x;
    const int slice = blockIdx.y;
    const int tid   = threadIdx.x;
    const float* p  = pred + (size_t)img * NPRED * PRED_C;

    if (tid == 0) cnt = 0;
    __syncthreads();

    const int base = slice * ROWS_SL;
    #pragma unroll
    for (int r = 0; r < 4; r++) {
        int row = tid + r * FILT_T;
        if (row < ROWS_SL) {
            int i = base + row;
            float obj = p[i * PRED_C + 4];
            float cls = p[i * PRED_C + 5];
            float conf = __fmul_rn(obj, cls);
            if (obj > CONF_T && conf > CONF_T) {
                int pos = atomicAdd(&cnt, 1);
                buf[pos] = ((u64)__float_as_uint(conf) << 32) |
                           (u64)(0xFFFFFFFFu - (u32)i);
            }
        }
    }
    __syncthreads();

    int n = cnt;
    if (tid == 0) g_cnt[img * NSLICE + slice] = n;
    u64* dst = g_cand + (size_t)(img * NSLICE + slice) * ROWS_SL;
    for (int k = tid; k < n; k += FILT_T) dst[k] = buf[k];
}

// ============================================================
// 2) sort: gather, histogram-select ~top-1000, bitonic sort 1024
// ============================================================
__global__ __launch_bounds__(SORT_T, 1)
void k_sort(const float* __restrict__ pred)
{
    extern __shared__ unsigned char sraw[];
    u64* skey  = (u64*)sraw;                          // 4096
    u64* skey2 = skey + CANDCAP;                      // SEL_N
    u32* hist  = (u32*)(skey2 + SEL_N);               // 1024
    u32* hist2 = hist + 1024;                         // 1024
    int* spfx  = (int*)(hist2 + 1024);                // 33
    int* misc  = spfx + 33;                           // [0]=total [1]=T [2]=kept

    const int img = blockIdx.x;
    const int tid = threadIdx.x;
    const float* p = pred + (size_t)img * NPRED * PRED_C;

    // prefix over slice counts (warp 0)
    if (tid < 32) {
        int c = (tid < NSLICE) ? g_cnt[img * NSLICE + tid] : 0;
        int x = c;
        #pragma unroll
        for (int d = 1; d < 32; d <<= 1) {
            int y = __shfl_up_sync(0xFFFFFFFFu, x, d);
            if ((tid & 31) >= d) x += y;
        }
        spfx[tid + 1] = x;
        if (tid == 0) spfx[0] = 0;
        if (tid == 31) misc[0] = x;
    }
    __syncthreads();

    int total = misc[0];
    if (total > CANDCAP) total = CANDCAP;

    // gather candidate keys
    for (int s = 0; s < NSLICE; s++) {
        int b0 = spfx[s], b1 = spfx[s + 1];
        const u64* src = g_cand + (size_t)(img * NSLICE + s) * ROWS_SL;
        for (int k = b0 + tid; k < b1; k += SORT_T)
            if (k < CANDCAP) skey[k] = src[k - b0];
    }
    for (int k = total + tid; k < CANDCAP; k += SORT_T) skey[k] = 0ull;
    hist[tid] = 0;
    __syncthreads();

    // histogram of conf bits (monotonic bins)
    for (int k = tid; k < total; k += SORT_T) {
        u32 bits = (u32)(skey[k] >> 32);
        int b = (int)((bits - 0x3F000000u) >> 13);
        b = b < 0 ? 0 : (b > 1023 ? 1023 : b);
        atomicAdd(&hist[b], 1u);
    }
    __syncthreads();

    // suffix sums
    u32 *ha = hist, *hb = hist2;
    for (int d = 1; d < 1024; d <<= 1) {
        u32 v = ha[tid] + ((tid + d < 1024) ? ha[tid + d] : 0u);
        hb[tid] = v;
        __syncthreads();
        u32* t = ha; ha = hb; hb = t;
    }
    int need = total < TOPK ? total : TOPK;
    if ((int)ha[tid] >= need && (tid == 1023 || (int)ha[tid + 1] < need))
        misc[1] = tid;
    if (tid == 0) misc[2] = 0;
    __syncthreads();

    int T = misc[1];
    int kept = (int)ha[T];
    bool fallback = (kept > SEL_N);

    u64* sbuf; int n;
    if (!fallback) {
        for (int k = tid; k < total; k += SORT_T) {
            u64 key = skey[k];
            u32 bits = (u32)(key >> 32);
            int b = (int)((bits - 0x3F000000u) >> 13);
            b = b < 0 ? 0 : (b > 1023 ? 1023 : b);
            if (b >= T) {
                int pos = atomicAdd(&misc[2], 1);
                skey2[pos] = key;
            }
        }
        __syncthreads();
        for (int k = kept + tid; k < SEL_N; k += SORT_T) skey2[k] = 0ull;
        sbuf = skey2; n = SEL_N;
    } else {
        sbuf = skey; n = CANDCAP;
    }
    __syncthreads();

    // bitonic sort descending
    for (int k = 2; k <= n; k <<= 1) {
        for (int j = k >> 1; j > 0; j >>= 1) {
            for (int q = 0; q < n; q += SORT_T) {
                int i = tid + q;
                if (i < n) {
                    int ixj = i ^ j;
                    if (ixj > i) {
                        u64 a = sbuf[i], b = sbuf[ixj];
                        if (((i & k) == 0) ? (a < b) : (a > b)) {
                            sbuf[i] = b; sbuf[ixj] = a;
                        }
                    }
                }
            }
            __syncthreads();
        }
    }

    // extract top-1000
    if (tid < TOPK) {
        u64 key = sbuf[tid];
        float4 b; float sc, ar; int idx;
        if ((key >> 32) != 0ull) {
            idx = (int)(0xFFFFFFFFu - (u32)(key & 0xFFFFFFFFull));
            sc  = __uint_as_float((u32)(key >> 32));
            float x = p[idx * PRED_C + 0];
            float y = p[idx * PRED_C + 1];
            float w = p[idx * PRED_C + 2];
            float h = p[idx * PRED_C + 3];
            float hw = __fmul_rn(w, 0.5f);
            float hh = __fmul_rn(h, 0.5f);
            b = make_float4(__fsub_rn(x, hw), __fsub_rn(y, hh),
                            __fadd_rn(x, hw), __fadd_rn(y, hh));
            ar = __fmul_rn(__fsub_rn(b.z, b.x), __fsub_rn(b.w, b.y));
        } else {
            idx = -1; sc = -1.0f; ar = 0.0f;
            b = make_float4(0.f, 0.f, 0.f, 0.f);
        }
        g_box  [img * 1024 + tid] = b;
        g_score[img * 1024 + tid] = sc;
        g_area [img * 1024 + tid] = ar;
        g_idx  [img * 1024 + tid] = idx;
    }
}

// ============================================================
// 3) mask: balanced upper-triangle (row, word) tasks, ballot per word
// ============================================================
__global__ __launch_bounds__(MASK_T)
void k_mask()
{
    __shared__ float4 sbox[TOPK];
    __shared__ float  sarea[TOPK];

    const int img  = blockIdx.x;
    const int tid  = threadIdx.x;
    const int lane = tid & 31;
    const int gw   = blockIdx.y * (MASK_T / 32) + (tid >> 5);  // 0..NWARPS_M-1

    for (int i = tid; i < TOPK; i += MASK_T) {
        sbox[i]  = g_box [img * 1024 + i];
        sarea[i] = g_area[img * 1024 + i];
    }
    __syncthreads();

    u32* gm = g_mask + (size_t)img * TOPK * MASKW;

    int u    = (int)(((long long)gw * TASKS) / NWARPS_M);
    int uend = (int)(((long long)(gw + 1) * TASKS) / NWARPS_M);

    int w = 0, acc = 0;
    while (true) {
        int cw = 32 * w + 32; if (cw > TOPK) cw = TOPK;
        if (acc + cw > u) break;
        acc += cw; w++;
    }
    int i  = u - acc;
    int cw = 32 * w + 32; if (cw > TOPK) cw = TOPK;

    int j = w * 32 + lane;
    bool jv = (j < TOPK);
    float4 bj = sbox[jv ? j : 0];
    float  aj = sarea[jv ? j : 0];

    for (; u < uend; ++u) {
        if (i == cw) {
            w++; i = 0;
            cw = 32 * w + 32; if (cw > TOPK) cw = TOPK;
            j = w * 32 + lane;
            jv = (j < TOPK);
            bj = sbox[jv ? j : 0];
            aj = sarea[jv ? j : 0];
        }
        float4 bi = sbox[i];
        float  ai = sarea[i];
        float lx = fmaxf(bi.x, bj.x);
        float ly = fmaxf(bi.y, bj.y);
        float rx = fminf(bi.z, bj.z);
        float ry = fminf(bi.w, bj.w);
        float iw = fmaxf(__fsub_rn(rx, lx), 0.0f);
        float ih = fmaxf(__fsub_rn(ry, ly), 0.0f);
        float inter = __fmul_rn(iw, ih);
        bool sup = false;
        if (j > i && jv && inter > 0.0f) {
            float denom = __fadd_rn(__fsub_rn(__fadd_rn(ai, aj), inter), 1e-7f);
            sup = (__fdiv_rn(inter, denom) > IOU_T);
        }
        u32 word = __ballot_sync(0xFFFFFFFFu, sup);
        if (lane == 0) gm[i * MASKW + w] = word;
        i++;
    }
}

// ============================================================
// 4) sweep: register-diagonal greedy (O(1)/chunk chain) + outputs
// ============================================================
__global__ __launch_bounds__(SWEEP_T, 1)
void k_sweep(const float* __restrict__ pred,
             float* __restrict__ out,
             float* __restrict__ keep_out)
{
    extern __shared__ unsigned char sraw[];
    u32* smask  = (u32*)sraw;                 // 1024*32 words (rows >=1000 zeroed)
    u32* svalid = smask + 1024 * MASKW;       // 32
    u32* skeep  = svalid + 32;                // 32

    const int img  = blockIdx.x;
    const int tid  = threadIdx.x;
    const int warp = tid >> 5, lane = tid & 31;

    // mask fill (L2-resident), vectorized; zero pad rows 1000..1023
    {
        const uint4* src = (const uint4*)(g_mask + (size_t)img * TOPK * MASKW);
        uint4* dst = (uint4*)smask;
        for (int k = tid; k < TOPK * MASKW / 4; k += SWEEP_T) dst[k] = src[k];
        for (int k = TOPK * MASKW + tid; k < 1024 * MASKW; k += SWEEP_T) smask[k] = 0;
    }

    // validity ballots
    for (int k = 0; k < 1024; k += SWEEP_T) {
        int t = k + tid;
        float sc = (t < TOPK) ? g_score[img * 1024 + t] : -1.0f;
        u32 vb = __ballot_sync(0xFFFFFFFFu, sc > CONF_T);
        if (lane == 0) svalid[(k >> 5) + warp] = vb;
    }
    __syncthreads();

    if (warp == 0) {
        u32 remv = 0;            // lane owns removal word `lane`
        u32 diag[32];            // chunk's 32x32 diagonal block, broadcast in regs
        #pragma unroll
        for (int b = 0; b < 32; b++) diag[b] = smask[b * 32 + 0];

        for (int w = 0; w < 32; w++) {
            u32 cur = __shfl_sync(0xFFFFFFFFu, remv, w);
            u32 alive = svalid[w] & ~cur;
            // serial greedy within chunk: pure register chain
            #pragma unroll
            for (int b = 0; b < 32; b++)
                if (alive & (1u << b)) alive &= ~diag[b];
            // prefetch next chunk's diagonal block
            if (w < 31) {
                #pragma unroll
                for (int b = 0; b < 32; b++)
                    diag[b] = smask[((w + 1) * 32 + b) * 32 + (w + 1)];
            }
            if (lane == 0) skeep[w] = alive;
            // accumulate suppression from kept items (independent LDS, pipelined)
            u32 m = alive;
            while (m) {
                int b = __ffs(m) - 1;
                m &= m - 1;
                remv |= smask[(w * 32 + b) * 32 + lane];
            }
        }
    }
    __syncthreads();

    const float* p = pred + (size_t)img * NPRED * PRED_C;
    for (int t = tid; t < TOPK; t += SWEEP_T) {
        bool kp = (skeep[t >> 5] >> (t & 31)) & 1u;
        float o0=0.f,o1=0.f,o2=0.f,o3=0.f,o4=0.f,o6=0.f,o7=0.f,o8=0.f;
        if (kp) {
            float4 b = g_box[img * 1024 + t];
            o0 = b.x; o1 = b.y; o2 = b.z; o3 = b.w;
            o4 = g_score[img * 1024 + t];
            int idx = g_idx[img * 1024 + t];
            o6 = p[idx * PRED_C + 6];
            o7 = p[idx * PRED_C + 7];
            o8 = p[idx * PRED_C + 8];
        }
        float* orow = out + ((size_t)img * TOPK + t) * PRED_C;
        orow[0]=o0; orow[1]=o1; orow[2]=o2; orow[3]=o3;
        orow[4]=o4; orow[5]=0.0f;
        orow[6]=o6; orow[7]=o7; orow[8]=o8;
        keep_out[(size_t)img * TOPK + t] = kp ? 1.0f : 0.0f;
    }
}

extern "C" void kernel_launch(void* const* d_in, const int* in_sizes, int n_in,
                              void* d_out, int out_size)
{
    const float* pred = (const float*)d_in[0];
    int B = in_sizes[0] / (NPRED * PRED_C);

    float* out  = (float*)d_out;
    float* keep = out + (size_t)B * TOPK * PRED_C;

    size_t smemSort  = (size_t)CANDCAP * 8 + SEL_N * 8 + 1024 * 4 * 2 + 80 * 4;
    size_t smemSweep = (size_t)1024 * MASKW * 4 + 64 * 4;

    static bool attr_set = false;
    if (!attr_set) {
        cudaFuncSetAttribute(k_sort,  cudaFuncAttributeMaxDynamicSharedMemorySize,
                             (int)smemSort);
        cudaFuncSetAttribute(k_sweep, cudaFuncAttributeMaxDynamicSharedMemorySize,
                             (int)smemSweep);
        attr_set = true;
    }

    k_filter<<<dim3(B, NSLICE), FILT_T>>>(pred);
    k_sort<<<B, SORT_T, smemSort>>>(pred);
    k_mask<<<dim3(B, MSLICES), MASK_T>>>();
    k_sweep<<<B, SWEEP_T, smemSweep>>>(pred, out, keep);
}

// round 5
// speedup vs baseline: 6.3225x; 1.0492x over previous
#include <cuda_runtime.h>
#include <stdint.h>

#define NPRED    25200
#define PRED_C   9
#define TOPK     1000
#define CONF_T   0.7f
#define IOU_T    0.45f
#define MASKW    32
#define BMAX     32

#define NSLICE   25
#define ROWS_SL  1008
#define FILT_T   256

#define CANDCAP  4096
#define SEL_N    1024
#define SORT_T   1024

#define MSLICES  16
#define MASK_T   256
#define NWARPS_M (MSLICES * (MASK_T / 32))    // 128 warps per image
#define TASKS    16872                        // sum_w min(1000, 32w+32)

#define SWEEP_T  512

typedef unsigned long long u64;
typedef unsigned int u32;

// ---------------- global scratch ----------------
__device__ int    g_cnt [BMAX * NSLICE];
__device__ u64    g_cand[BMAX * NSLICE * ROWS_SL];
__device__ float4 g_box [BMAX * 1024];
__device__ float  g_score[BMAX * 1024];
__device__ float  g_area[BMAX * 1024];
__device__ int    g_idx [BMAX * 1024];
__device__ u32    g_mask[BMAX * TOPK * MASKW];   // lower-triangle words never written (stay 0)

// ============================================================
// 1) filter: full-chip pass over predictions
// ============================================================
__global__ __launch_bounds__(FILT_T)
void k_filter(const float* __restrict__ pred)
{
    __shared__ u64 buf[ROWS_SL];
    __shared__ int cnt;

    const int img   = blockIdx.x;
    const int slice = blockIdx.y;
    const int tid   = threadIdx.x;
    const float* p  = pred + (size_t)img * NPRED * PRED_C;

    if (tid == 0) cnt = 0;
    __syncthreads();

    const int base = slice * ROWS_SL;
    #pragma unroll
    for (int r = 0; r < 4; r++) {
        int row = tid + r * FILT_T;
        if (row < ROWS_SL) {
            int i = base + row;
            float obj = p[i * PRED_C + 4];
            float cls = p[i * PRED_C + 5];
            float conf = __fmul_rn(obj, cls);
            if (obj > CONF_T && conf > CONF_T) {
                int pos = atomicAdd(&cnt, 1);
                buf[pos] = ((u64)__float_as_uint(conf) << 32) |
                           (u64)(0xFFFFFFFFu - (u32)i);
            }
        }
    }
    __syncthreads();

    int n = cnt;
    if (tid == 0) g_cnt[img * NSLICE + slice] = n;
    u64* dst = g_cand + (size_t)(img * NSLICE + slice) * ROWS_SL;
    for (int k = tid; k < n; k += FILT_T) dst[k] = buf[k];
}

// ============================================================
// 2) sort: gather, histogram-select, hybrid shfl/smem bitonic
// ============================================================
__global__ __launch_bounds__(SORT_T, 1)
void k_sort(const float* __restrict__ pred)
{
    extern __shared__ unsigned char sraw[];
    u64* skey  = (u64*)sraw;                          // 4096
    u64* skey2 = skey + CANDCAP;                      // SEL_N
    u32* hist  = (u32*)(skey2 + SEL_N);               // 1024
    u32* hist2 = hist + 1024;                         // 1024
    int* spfx  = (int*)(hist2 + 1024);                // 33
    int* misc  = spfx + 33;                           // [0]=total [1]=T [2]=kept

    const int img = blockIdx.x;
    const int tid = threadIdx.x;
    const float* p = pred + (size_t)img * NPRED * PRED_C;

    // prefix over slice counts (warp 0)
    if (tid < 32) {
        int c = (tid < NSLICE) ? g_cnt[img * NSLICE + tid] : 0;
        int x = c;
        #pragma unroll
        for (int d = 1; d < 32; d <<= 1) {
            int y = __shfl_up_sync(0xFFFFFFFFu, x, d);
            if ((tid & 31) >= d) x += y;
        }
        spfx[tid + 1] = x;
        if (tid == 0) spfx[0] = 0;
        if (tid == 31) misc[0] = x;
    }
    __syncthreads();

    int total = misc[0];
    if (total > CANDCAP) total = CANDCAP;

    // gather candidate keys
    for (int s = 0; s < NSLICE; s++) {
        int b0 = spfx[s], b1 = spfx[s + 1];
        const u64* src = g_cand + (size_t)(img * NSLICE + s) * ROWS_SL;
        for (int k = b0 + tid; k < b1; k += SORT_T)
            if (k < CANDCAP) skey[k] = src[k - b0];
    }
    for (int k = total + tid; k < CANDCAP; k += SORT_T) skey[k] = 0ull;
    hist[tid] = 0;
    __syncthreads();

    // histogram of conf bits (monotonic bins)
    for (int k = tid; k < total; k += SORT_T) {
        u32 bits = (u32)(skey[k] >> 32);
        int b = (int)((bits - 0x3F000000u) >> 13);
        b = b < 0 ? 0 : (b > 1023 ? 1023 : b);
        atomicAdd(&hist[b], 1u);
    }
    __syncthreads();

    // suffix sums
    u32 *ha = hist, *hb = hist2;
    for (int d = 1; d < 1024; d <<= 1) {
        u32 v = ha[tid] + ((tid + d < 1024) ? ha[tid + d] : 0u);
        hb[tid] = v;
        __syncthreads();
        u32* t = ha; ha = hb; hb = t;
    }
    int need = total < TOPK ? total : TOPK;
    if ((int)ha[tid] >= need && (tid == 1023 || (int)ha[tid + 1] < need))
        misc[1] = tid;
    if (tid == 0) misc[2] = 0;
    __syncthreads();

    int T = misc[1];
    int kept = (int)ha[T];
    bool fallback = (kept > SEL_N);

    u64* sbuf;
    if (!fallback) {
        for (int k = tid; k < total; k += SORT_T) {
            u64 key = skey[k];
            u32 bits = (u32)(key >> 32);
            int b = (int)((bits - 0x3F000000u) >> 13);
            b = b < 0 ? 0 : (b > 1023 ? 1023 : b);
            if (b >= T) {
                int pos = atomicAdd(&misc[2], 1);
                skey2[pos] = key;
            }
        }
        __syncthreads();
        for (int k = kept + tid; k < SEL_N; k += SORT_T) skey2[k] = 0ull;
        sbuf = skey2;
        __syncthreads();

        // ---- fast hybrid bitonic: 1 element/thread, shfl for j<=16 ----
        u64 v = sbuf[tid];
        // k = 2..32: all substeps within a warp
        #pragma unroll
        for (int k = 2; k <= 32; k <<= 1) {
            #pragma unroll
            for (int j = k >> 1; j > 0; j >>= 1) {
                u64 o = __shfl_xor_sync(0xFFFFFFFFu, v, j);
                bool keep_max = ((tid & j) == 0) == ((tid & k) == 0);
                bool vbig = v > o;
                v = (keep_max == vbig) ? v : o;
            }
        }
        // k = 64..1024: j>=32 via smem, j<=16 via shfl
        #pragma unroll
        for (int k = 64; k <= SEL_N; k <<= 1) {
            for (int j = k >> 1; j >= 32; j >>= 1) {
                sbuf[tid] = v;
                __syncthreads();
                u64 o = sbuf[tid ^ j];
                bool keep_max = ((tid & j) == 0) == ((tid & k) == 0);
                bool vbig = v > o;
                v = (keep_max == vbig) ? v : o;
                __syncthreads();
            }
            #pragma unroll
            for (int j = 16; j > 0; j >>= 1) {
                u64 o = __shfl_xor_sync(0xFFFFFFFFu, v, j);
                bool keep_max = ((tid & j) == 0) == ((tid & k) == 0);
                bool vbig = v > o;
                v = (keep_max == vbig) ? v : o;
            }
        }
        sbuf[tid] = v;
        __syncthreads();
    } else {
        sbuf = skey;
        const int n = CANDCAP;
        __syncthreads();
        for (int k = 2; k <= n; k <<= 1) {
            for (int j = k >> 1; j > 0; j >>= 1) {
                for (int q = 0; q < n; q += SORT_T) {
                    int i = tid + q;
                    int ixj = i ^ j;
                    if (ixj > i) {
                        u64 a = sbuf[i], b = sbuf[ixj];
                        if (((i & k) == 0) ? (a < b) : (a > b)) {
                            sbuf[i] = b; sbuf[ixj] = a;
                        }
                    }
                }
                __syncthreads();
            }
        }
    }

    // extract top-1000
    if (tid < TOPK) {
        u64 key = sbuf[tid];
        float4 b; float sc, ar; int idx;
        if ((key >> 32) != 0ull) {
            idx = (int)(0xFFFFFFFFu - (u32)(key & 0xFFFFFFFFull));
            sc  = __uint_as_float((u32)(key >> 32));
            float x = p[idx * PRED_C + 0];
            float y = p[idx * PRED_C + 1];
            float w = p[idx * PRED_C + 2];
            float h = p[idx * PRED_C + 3];
            float hw = __fmul_rn(w, 0.5f);
            float hh = __fmul_rn(h, 0.5f);
            b = make_float4(__fsub_rn(x, hw), __fsub_rn(y, hh),
                            __fadd_rn(x, hw), __fadd_rn(y, hh));
            ar = __fmul_rn(__fsub_rn(b.z, b.x), __fsub_rn(b.w, b.y));
        } else {
            idx = -1; sc = -1.0f; ar = 0.0f;
            b = make_float4(0.f, 0.f, 0.f, 0.f);
        }
        g_box  [img * 1024 + tid] = b;
        g_score[img * 1024 + tid] = sc;
        g_area [img * 1024 + tid] = ar;
        g_idx  [img * 1024 + tid] = idx;
    }
}

// ============================================================
// 3) mask: balanced upper-triangle (row, word) tasks, ballot per word
// ============================================================
__global__ __launch_bounds__(MASK_T)
void k_mask()
{
    __shared__ float4 sbox[TOPK];
    __shared__ float  sarea[TOPK];

    const int img  = blockIdx.x;
    const int tid  = threadIdx.x;
    const int lane = tid & 31;
    const int gw   = blockIdx.y * (MASK_T / 32) + (tid >> 5);

    for (int i = tid; i < TOPK; i += MASK_T) {
        sbox[i]  = g_box [img * 1024 + i];
        sarea[i] = g_area[img * 1024 + i];
    }
    __syncthreads();

    u32* gm = g_mask + (size_t)img * TOPK * MASKW;

    int u    = (int)(((long long)gw * TASKS) / NWARPS_M);
    int uend = (int)(((long long)(gw + 1) * TASKS) / NWARPS_M);

    int w = 0, acc = 0;
    while (true) {
        int cw = 32 * w + 32; if (cw > TOPK) cw = TOPK;
        if (acc + cw > u) break;
        acc += cw; w++;
    }
    int i  = u - acc;
    int cw = 32 * w + 32; if (cw > TOPK) cw = TOPK;

    int j = w * 32 + lane;
    bool jv = (j < TOPK);
    float4 bj = sbox[jv ? j : 0];
    float  aj = sarea[jv ? j : 0];

    for (; u < uend; ++u) {
        if (i == cw) {
            w++; i = 0;
            cw = 32 * w + 32; if (cw > TOPK) cw = TOPK;
            j = w * 32 + lane;
            jv = (j < TOPK);
            bj = sbox[jv ? j : 0];
            aj = sarea[jv ? j : 0];
        }
        float4 bi = sbox[i];
        float  ai = sarea[i];
        float lx = fmaxf(bi.x, bj.x);
        float ly = fmaxf(bi.y, bj.y);
        float rx = fminf(bi.z, bj.z);
        float ry = fminf(bi.w, bj.w);
        float iw = fmaxf(__fsub_rn(rx, lx), 0.0f);
        float ih = fmaxf(__fsub_rn(ry, ly), 0.0f);
        float inter = __fmul_rn(iw, ih);
        bool sup = false;
        if (j > i && jv && inter > 0.0f) {
            float denom = __fadd_rn(__fsub_rn(__fadd_rn(ai, aj), inter), 1e-7f);
            sup = (__fdiv_rn(inter, denom) > IOU_T);
        }
        u32 word = __ballot_sync(0xFFFFFFFFu, sup);
        if (lane == 0) gm[i * MASKW + w] = word;
        i++;
    }
}

// ============================================================
// 4) sweep: contiguous-diag branchless greedy + outputs
// ============================================================
#define STEP(b, d) { u32 s = (u32)((int)(alive << (31 - (b))) >> 31); \
                     alive &= ~((d) & s); }

__global__ __launch_bounds__(SWEEP_T, 1)
void k_sweep(const float* __restrict__ pred,
             float* __restrict__ out,
             float* __restrict__ keep_out)
{
    extern __shared__ unsigned char sraw[];
    u32* smask  = (u32*)sraw;                 // 1024*32 (pad rows zeroed)
    u32* sdiag  = smask + 1024 * MASKW;       // 1024 (contiguous per-chunk diag)
    u32* svalid = sdiag + 1024;               // 32
    u32* skeep  = svalid + 32;                // 32

    const int img  = blockIdx.x;
    const int tid  = threadIdx.x;
    const int warp = tid >> 5, lane = tid & 31;

    // mask fill (L2-resident), vectorized; zero pad rows 1000..1023
    {
        const uint4* src = (const uint4*)(g_mask + (size_t)img * TOPK * MASKW);
        uint4* dst = (uint4*)smask;
        for (int k = tid; k < TOPK * MASKW / 4; k += SWEEP_T) dst[k] = src[k];
        for (int k = TOPK * MASKW + tid; k < 1024 * MASKW; k += SWEEP_T) smask[k] = 0;
    }

    // validity ballots
    for (int k = 0; k < 1024; k += SWEEP_T) {
        int t = k + tid;
        float sc = (t < TOPK) ? g_score[img * 1024 + t] : -1.0f;
        u32 vb = __ballot_sync(0xFFFFFFFFu, sc > CONF_T);
        if (lane == 0) svalid[(t >> 5)] = vb;
    }
    __syncthreads();

    // contiguous diag extraction: sdiag[t] = smask[t*32 + (t>>5)]
    for (int t = tid; t < 1024; t += SWEEP_T)
        sdiag[t] = smask[t * 32 + (t >> 5)];
    __syncthreads();

    if (warp == 0) {
        u32 remv = 0;                      // lane owns removal word `lane`
        for (int w = 0; w < 32; w++) {
            const uint4* dq = (const uint4*)(sdiag + w * 32);
            uint4 q0 = dq[0], q1 = dq[1], q2 = dq[2], q3 = dq[3];
            uint4 q4 = dq[4], q5 = dq[5], q6 = dq[6], q7 = dq[7];
            u32 cur = __shfl_sync(0xFFFFFFFFu, remv, w);
            u32 alive = svalid[w] & ~cur;
            STEP( 0, q0.x) STEP( 1, q0.y) STEP( 2, q0.z) STEP( 3, q0.w)
            STEP( 4, q1.x) STEP( 5, q1.y) STEP( 6, q1.z) STEP( 7, q1.w)
            STEP( 8, q2.x) STEP( 9, q2.y) STEP(10, q2.z) STEP(11, q2.w)
            STEP(12, q3.x) STEP(13, q3.y) STEP(14, q3.z) STEP(15, q3.w)
            STEP(16, q4.x) STEP(17, q4.y) STEP(18, q4.z) STEP(19, q4.w)
            STEP(20, q5.x) STEP(21, q5.y) STEP(22, q5.z) STEP(23, q5.w)
            STEP(24, q6.x) STEP(25, q6.y) STEP(26, q6.z) STEP(27, q6.w)
            STEP(28, q7.x) STEP(29, q7.y) STEP(30, q7.z) STEP(31, q7.w)
            if (lane == 0) skeep[w] = alive;
            u32 m = alive;
            while (m) {
                int b = __ffs(m) - 1;
                m &= m - 1;
                remv |= smask[(w * 32 + b) * 32 + lane];
            }
        }
    }
    __syncthreads();

    const float* p = pred + (size_t)img * NPRED * PRED_C;
    for (int t = tid; t < TOPK; t += SWEEP_T) {
        bool kp = (skeep[t >> 5] >> (t & 31)) & 1u;
        float o0=0.f,o1=0.f,o2=0.f,o3=0.f,o4=0.f,o6=0.f,o7=0.f,o8=0.f;
        if (kp) {
            float4 b = g_box[img * 1024 + t];
            o0 = b.x; o1 = b.y; o2 = b.z; o3 = b.w;
            o4 = g_score[img * 1024 + t];
            int idx = g_idx[img * 1024 + t];
            o6 = p[idx * PRED_C + 6];
            o7 = p[idx * PRED_C + 7];
            o8 = p[idx * PRED_C + 8];
        }
        float* orow = out + ((size_t)img * TOPK + t) * PRED_C;
        orow[0]=o0; orow[1]=o1; orow[2]=o2; orow[3]=o3;
        orow[4]=o4; orow[5]=0.0f;
        orow[6]=o6; orow[7]=o7; orow[8]=o8;
        keep_out[(size_t)img * TOPK + t] = kp ? 1.0f : 0.0f;
    }
}

extern "C" void kernel_launch(void* const* d_in, const int* in_sizes, int n_in,
                              void* d_out, int out_size)
{
    const float* pred = (const float*)d_in[0];
    int B = in_sizes[0] / (NPRED * PRED_C);

    float* out  = (float*)d_out;
    float* keep = out + (size_t)B * TOPK * PRED_C;

    size_t smemSort  = (size_t)CANDCAP * 8 + SEL_N * 8 + 1024 * 4 * 2 + 80 * 4;
    size_t smemSweep = (size_t)1024 * MASKW * 4 + 1024 * 4 + 64 * 4;

    static bool attr_set = false;
    if (!attr_set) {
        cudaFuncSetAttribute(k_sort,  cudaFuncAttributeMaxDynamicSharedMemorySize,
                             (int)smemSort);
        cudaFuncSetAttribute(k_sweep, cudaFuncAttributeMaxDynamicSharedMemorySize,
                             (int)smemSweep);
        attr_set = true;
    }

    k_filter<<<dim3(B, NSLICE), FILT_T>>>(pred);
    k_sort<<<B, SORT_T, smemSort>>>(pred);
    k_mask<<<dim3(B, MSLICES), MASK_T>>>();
    k_sweep<<<B, SWEEP_T, smemSweep>>>(pred, out, keep);
}

// round 6
// speedup vs baseline: 8.3318x; 1.3178x over previous
#include <cuda_runtime.h>
#include <stdint.h>

#define NPRED    25200
#define PRED_C   9
#define TOPK     1000
#define CONF_T   0.7f
#define IOU_T    0.45f
#define MASKW    32
#define BMAX     32

#define NSLICE   25
#define ROWS_SL  1008
#define FILT_T   256

#define CANDCAP  4096
#define SEL_N    1024
#define SORT_T   1024

#define MSLICES  16
#define MASK_T   256
#define NWARPS_M (MSLICES * (MASK_T / 32))    // 128 warps per image
#define TASKS    16872                        // sum_w min(1000, 32w+32)

#define SWEEP_T  512

typedef unsigned long long u64;
typedef unsigned int u32;

// ---------------- global scratch ----------------
__device__ int    g_cnt [BMAX * NSLICE];
__device__ u64    g_cand[BMAX * NSLICE * ROWS_SL];
__device__ float4 g_box [BMAX * 1024];
__device__ float  g_score[BMAX * 1024];
__device__ float  g_area[BMAX * 1024];
__device__ int    g_idx [BMAX * 1024];
__device__ u32    g_mask[BMAX * TOPK * MASKW];   // lower-triangle words never written (stay 0)

// ============================================================
// 1) filter: full-chip pass over predictions
// ============================================================
__global__ __launch_bounds__(FILT_T)
void k_filter(const float* __restrict__ pred)
{
    __shared__ u64 buf[ROWS_SL];
    __shared__ int cnt;

    const int img   = blockIdx.x;
    const int slice = blockIdx.y;
    const int tid   = threadIdx.x;
    const float* p  = pred + (size_t)img * NPRED * PRED_C;

    if (tid == 0) cnt = 0;
    __syncthreads();

    const int base = slice * ROWS_SL;
    #pragma unroll
    for (int r = 0; r < 4; r++) {
        int row = tid + r * FILT_T;
        if (row < ROWS_SL) {
            int i = base + row;
            float obj = p[i * PRED_C + 4];
            float cls = p[i * PRED_C + 5];
            float conf = __fmul_rn(obj, cls);
            if (obj > CONF_T && conf > CONF_T) {
                int pos = atomicAdd(&cnt, 1);
                buf[pos] = ((u64)__float_as_uint(conf) << 32) |
                           (u64)(0xFFFFFFFFu - (u32)i);
            }
        }
    }
    __syncthreads();

    int n = cnt;
    if (tid == 0) g_cnt[img * NSLICE + slice] = n;
    u64* dst = g_cand + (size_t)(img * NSLICE + slice) * ROWS_SL;
    for (int k = tid; k < n; k += FILT_T) dst[k] = buf[k];
}

// ============================================================
// 2) sort: gather, histogram-select, hybrid shfl/smem bitonic
// ============================================================
__global__ __launch_bounds__(SORT_T, 1)
void k_sort(const float* __restrict__ pred)
{
    extern __shared__ unsigned char sraw[];
    u64* skey  = (u64*)sraw;                          // 4096
    u64* skey2 = skey + CANDCAP;                      // SEL_N
    u32* hist  = (u32*)(skey2 + SEL_N);               // 1024
    u32* hist2 = hist + 1024;                         // 1024
    int* spfx  = (int*)(hist2 + 1024);                // 33
    int* misc  = spfx + 33;                           // [0]=total [1]=T [2]=kept

    const int img = blockIdx.x;
    const int tid = threadIdx.x;
    const float* p = pred + (size_t)img * NPRED * PRED_C;

    // prefix over slice counts (warp 0)
    if (tid < 32) {
        int c = (tid < NSLICE) ? g_cnt[img * NSLICE + tid] : 0;
        int x = c;
        #pragma unroll
        for (int d = 1; d < 32; d <<= 1) {
            int y = __shfl_up_sync(0xFFFFFFFFu, x, d);
            if ((tid & 31) >= d) x += y;
        }
        spfx[tid + 1] = x;
        if (tid == 0) spfx[0] = 0;
        if (tid == 31) misc[0] = x;
    }
    __syncthreads();

    int total = misc[0];
    if (total > CANDCAP) total = CANDCAP;

    // gather candidate keys
    for (int s = 0; s < NSLICE; s++) {
        int b0 = spfx[s], b1 = spfx[s + 1];
        const u64* src = g_cand + (size_t)(img * NSLICE + s) * ROWS_SL;
        for (int k = b0 + tid; k < b1; k += SORT_T)
            if (k < CANDCAP) skey[k] = src[k - b0];
    }
    for (int k = total + tid; k < CANDCAP; k += SORT_T) skey[k] = 0ull;
    hist[tid] = 0;
    __syncthreads();

    // histogram of conf bits (monotonic bins)
    for (int k = tid; k < total; k += SORT_T) {
        u32 bits = (u32)(skey[k] >> 32);
        int b = (int)((bits - 0x3F000000u) >> 13);
        b = b < 0 ? 0 : (b > 1023 ? 1023 : b);
        atomicAdd(&hist[b], 1u);
    }
    __syncthreads();

    // suffix sums
    u32 *ha = hist, *hb = hist2;
    for (int d = 1; d < 1024; d <<= 1) {
        u32 v = ha[tid] + ((tid + d < 1024) ? ha[tid + d] : 0u);
        hb[tid] = v;
        __syncthreads();
        u32* t = ha; ha = hb; hb = t;
    }
    int need = total < TOPK ? total : TOPK;
    if ((int)ha[tid] >= need && (tid == 1023 || (int)ha[tid + 1] < need))
        misc[1] = tid;
    if (tid == 0) misc[2] = 0;
    __syncthreads();

    int T = misc[1];
    int kept = (int)ha[T];
    bool fallback = (kept > SEL_N);

    u64* sbuf;
    if (!fallback) {
        for (int k = tid; k < total; k += SORT_T) {
            u64 key = skey[k];
            u32 bits = (u32)(key >> 32);
            int b = (int)((bits - 0x3F000000u) >> 13);
            b = b < 0 ? 0 : (b > 1023 ? 1023 : b);
            if (b >= T) {
                int pos = atomicAdd(&misc[2], 1);
                skey2[pos] = key;
            }
        }
        __syncthreads();
        for (int k = kept + tid; k < SEL_N; k += SORT_T) skey2[k] = 0ull;
        sbuf = skey2;
        __syncthreads();

        // ---- fast hybrid bitonic: 1 element/thread, shfl for j<=16 ----
        u64 v = sbuf[tid];
        #pragma unroll
        for (int k = 2; k <= 32; k <<= 1) {
            #pragma unroll
            for (int j = k >> 1; j > 0; j >>= 1) {
                u64 o = __shfl_xor_sync(0xFFFFFFFFu, v, j);
                bool keep_max = ((tid & j) == 0) == ((tid & k) == 0);
                bool vbig = v > o;
                v = (keep_max == vbig) ? v : o;
            }
        }
        #pragma unroll
        for (int k = 64; k <= SEL_N; k <<= 1) {
            for (int j = k >> 1; j >= 32; j >>= 1) {
                sbuf[tid] = v;
                __syncthreads();
                u64 o = sbuf[tid ^ j];
                bool keep_max = ((tid & j) == 0) == ((tid & k) == 0);
                bool vbig = v > o;
                v = (keep_max == vbig) ? v : o;
                __syncthreads();
            }
            #pragma unroll
            for (int j = 16; j > 0; j >>= 1) {
                u64 o = __shfl_xor_sync(0xFFFFFFFFu, v, j);
                bool keep_max = ((tid & j) == 0) == ((tid & k) == 0);
                bool vbig = v > o;
                v = (keep_max == vbig) ? v : o;
            }
        }
        sbuf[tid] = v;
        __syncthreads();
    } else {
        sbuf = skey;
        const int n = CANDCAP;
        __syncthreads();
        for (int k = 2; k <= n; k <<= 1) {
            for (int j = k >> 1; j > 0; j >>= 1) {
                for (int q = 0; q < n; q += SORT_T) {
                    int i = tid + q;
                    int ixj = i ^ j;
                    if (ixj > i) {
                        u64 a = sbuf[i], b = sbuf[ixj];
                        if (((i & k) == 0) ? (a < b) : (a > b)) {
                            sbuf[i] = b; sbuf[ixj] = a;
                        }
                    }
                }
                __syncthreads();
            }
        }
    }

    // extract top-1000
    if (tid < TOPK) {
        u64 key = sbuf[tid];
        float4 b; float sc, ar; int idx;
        if ((key >> 32) != 0ull) {
            idx = (int)(0xFFFFFFFFu - (u32)(key & 0xFFFFFFFFull));
            sc  = __uint_as_float((u32)(key >> 32));
            float x = p[idx * PRED_C + 0];
            float y = p[idx * PRED_C + 1];
            float w = p[idx * PRED_C + 2];
            float h = p[idx * PRED_C + 3];
            float hw = __fmul_rn(w, 0.5f);
            float hh = __fmul_rn(h, 0.5f);
            b = make_float4(__fsub_rn(x, hw), __fsub_rn(y, hh),
                            __fadd_rn(x, hw), __fadd_rn(y, hh));
            ar = __fmul_rn(__fsub_rn(b.z, b.x), __fsub_rn(b.w, b.y));
        } else {
            idx = -1; sc = -1.0f; ar = 0.0f;
            b = make_float4(0.f, 0.f, 0.f, 0.f);
        }
        g_box  [img * 1024 + tid] = b;
        g_score[img * 1024 + tid] = sc;
        g_area [img * 1024 + tid] = ar;
        g_idx  [img * 1024 + tid] = idx;
    }
}

// ============================================================
// 3) mask: balanced upper-triangle (row, word) tasks, ballot per word
// ============================================================
__global__ __launch_bounds__(MASK_T)
void k_mask()
{
    __shared__ float4 sbox[TOPK];
    __shared__ float  sarea[TOPK];

    const int img  = blockIdx.x;
    const int tid  = threadIdx.x;
    const int lane = tid & 31;
    const int gw   = blockIdx.y * (MASK_T / 32) + (tid >> 5);

    for (int i = tid; i < TOPK; i += MASK_T) {
        sbox[i]  = g_box [img * 1024 + i];
        sarea[i] = g_area[img * 1024 + i];
    }
    __syncthreads();

    u32* gm = g_mask + (size_t)img * TOPK * MASKW;

    int u    = (int)(((long long)gw * TASKS) / NWARPS_M);
    int uend = (int)(((long long)(gw + 1) * TASKS) / NWARPS_M);

    int w = 0, acc = 0;
    while (true) {
        int cw = 32 * w + 32; if (cw > TOPK) cw = TOPK;
        if (acc + cw > u) break;
        acc += cw; w++;
    }
    int i  = u - acc;
    int cw = 32 * w + 32; if (cw > TOPK) cw = TOPK;

    int j = w * 32 + lane;
    bool jv = (j < TOPK);
    float4 bj = sbox[jv ? j : 0];
    float  aj = sarea[jv ? j : 0];

    for (; u < uend; ++u) {
        if (i == cw) {
            w++; i = 0;
            cw = 32 * w + 32; if (cw > TOPK) cw = TOPK;
            j = w * 32 + lane;
            jv = (j < TOPK);
            bj = sbox[jv ? j : 0];
            aj = sarea[jv ? j : 0];
        }
        float4 bi = sbox[i];
        float  ai = sarea[i];
        float lx = fmaxf(bi.x, bj.x);
        float ly = fmaxf(bi.y, bj.y);
        float rx = fminf(bi.z, bj.z);
        float ry = fminf(bi.w, bj.w);
        float iw = fmaxf(__fsub_rn(rx, lx), 0.0f);
        float ih = fmaxf(__fsub_rn(ry, ly), 0.0f);
        float inter = __fmul_rn(iw, ih);
        bool sup = false;
        if (j > i && jv && inter > 0.0f) {
            float denom = __fadd_rn(__fsub_rn(__fadd_rn(ai, aj), inter), 1e-7f);
            sup = (__fdiv_rn(inter, denom) > IOU_T);
        }
        u32 word = __ballot_sync(0xFFFFFFFFu, sup);
        if (lane == 0) gm[i * MASKW + w] = word;
        i++;
    }
}

// ============================================================
// 4) sweep: tiny-serial resolve + parallel accumulate per chunk
// ============================================================
#define STEP(b, d) { u32 s = (u32)((int)(alive << (31 - (b))) >> 31); \
                     alive &= ~((d) & s); }

__global__ __launch_bounds__(SWEEP_T, 1)
void k_sweep(const float* __restrict__ pred,
             float* __restrict__ out,
             float* __restrict__ keep_out)
{
    extern __shared__ unsigned char sraw[];
    u32* smask  = (u32*)sraw;                 // 1024*32 (pad rows zeroed)
    u32* sdiag  = smask + 1024 * MASKW;       // 1024 (contiguous per-chunk diag)
    u32* svalid = sdiag + 1024;               // 32
    u32* skeep  = svalid + 32;                // 32
    u32* sremv  = skeep + 32;                 // 32 (running removal words)
    u32* salive = sremv + 32;                 // 1

    const int img  = blockIdx.x;
    const int tid  = threadIdx.x;
    const int warp = tid >> 5, lane = tid & 31;

    // mask fill (L2-resident), vectorized; zero pad rows 1000..1023
    {
        const uint4* src = (const uint4*)(g_mask + (size_t)img * TOPK * MASKW);
        uint4* dst = (uint4*)smask;
        for (int k = tid; k < TOPK * MASKW / 4; k += SWEEP_T) dst[k] = src[k];
        for (int k = TOPK * MASKW + tid; k < 1024 * MASKW; k += SWEEP_T) smask[k] = 0;
    }

    // validity ballots
    for (int k = 0; k < 1024; k += SWEEP_T) {
        int t = k + tid;
        float sc = (t < TOPK) ? g_score[img * 1024 + t] : -1.0f;
        u32 vb = __ballot_sync(0xFFFFFFFFu, sc > CONF_T);
        if (lane == 0) svalid[t >> 5] = vb;
    }
    if (tid < 32) sremv[tid] = 0;
    __syncthreads();

    // contiguous diag extraction: sdiag[t] = smask[t*32 + (t>>5)]
    for (int t = tid; t < 1024; t += SWEEP_T)
        sdiag[t] = smask[t * 32 + (t >> 5)];
    __syncthreads();

    for (int w = 0; w < 32; w++) {
        // ---- tiny serial resolve (warp 0) ----
        if (warp == 0) {
            const uint4* dq = (const uint4*)(sdiag + w * 32);
            uint4 q0 = dq[0], q1 = dq[1], q2 = dq[2], q3 = dq[3];
            uint4 q4 = dq[4], q5 = dq[5], q6 = dq[6], q7 = dq[7];
            u32 alive = svalid[w] & ~sremv[w];
            STEP( 0, q0.x) STEP( 1, q0.y) STEP( 2, q0.z) STEP( 3, q0.w)
            STEP( 4, q1.x) STEP( 5, q1.y) STEP( 6, q1.z) STEP( 7, q1.w)
            STEP( 8, q2.x) STEP( 9, q2.y) STEP(10, q2.z) STEP(11, q2.w)
            STEP(12, q3.x) STEP(13, q3.y) STEP(14, q3.z) STEP(15, q3.w)
            STEP(16, q4.x) STEP(17, q4.y) STEP(18, q4.z) STEP(19, q4.w)
            STEP(20, q5.x) STEP(21, q5.y) STEP(22, q5.z) STEP(23, q5.w)
            STEP(24, q6.x) STEP(25, q6.y) STEP(26, q6.z) STEP(27, q6.w)
            STEP(28, q7.x) STEP(29, q7.y) STEP(30, q7.z) STEP(31, q7.w)
            if (lane == 0) { skeep[w] = alive; salive[0] = alive; }
        }
        __syncthreads();
        // ---- parallel accumulate of this chunk's kept rows (all warps) ----
        if (w < 31) {
            u32 a = salive[0];
            u32 mym = a & (3u << (warp * 2));   // 2 candidate bits per warp
            u32 partial = 0;
            while (mym) {
                int b = __ffs(mym) - 1;
                mym &= mym - 1;
                partial |= smask[(w * 32 + b) * 32 + lane];  // lane = word
            }
            if (partial) atomicOr(&sremv[lane], partial);
            __syncthreads();
        }
    }

    const float* p = pred + (size_t)img * NPRED * PRED_C;
    for (int t = tid; t < TOPK; t += SWEEP_T) {
        bool kp = (skeep[t >> 5] >> (t & 31)) & 1u;
        float o0=0.f,o1=0.f,o2=0.f,o3=0.f,o4=0.f,o6=0.f,o7=0.f,o8=0.f;
        if (kp) {
            float4 b = g_box[img * 1024 + t];
            o0 = b.x; o1 = b.y; o2 = b.z; o3 = b.w;
            o4 = g_score[img * 1024 + t];
            int idx = g_idx[img * 1024 + t];
            o6 = p[idx * PRED_C + 6];
            o7 = p[idx * PRED_C + 7];
            o8 = p[idx * PRED_C + 8];
        }
        float* orow = out + ((size_t)img * TOPK + t) * PRED_C;
        orow[0]=o0; orow[1]=o1; orow[2]=o2; orow[3]=o3;
        orow[4]=o4; orow[5]=0.0f;
        orow[6]=o6; orow[7]=o7; orow[8]=o8;
        keep_out[(size_t)img * TOPK + t] = kp ? 1.0f : 0.0f;
    }
}

extern "C" void kernel_launch(void* const* d_in, const int* in_sizes, int n_in,
                              void* d_out, int out_size)
{
    const float* pred = (const float*)d_in[0];
    int B = in_sizes[0] / (NPRED * PRED_C);

    float* out  = (float*)d_out;
    float* keep = out + (size_t)B * TOPK * PRED_C;

    size_t smemSort  = (size_t)CANDCAP * 8 + SEL_N * 8 + 1024 * 4 * 2 + 80 * 4;
    size_t smemSweep = (size_t)1024 * MASKW * 4 + 1024 * 4 + 128 * 4;

    static bool attr_set = false;
    if (!attr_set) {
        cudaFuncSetAttribute(k_sort,  cudaFuncAttributeMaxDynamicSharedMemorySize,
                             (int)smemSort);
        cudaFuncSetAttribute(k_sweep, cudaFuncAttributeMaxDynamicSharedMemorySize,
                             (int)smemSweep);
        attr_set = true;
    }

    k_filter<<<dim3(B, NSLICE), FILT_T>>>(pred);
    k_sort<<<B, SORT_T, smemSort>>>(pred);
    k_mask<<<dim3(B, MSLICES), MASK_T>>>();
    k_sweep<<<B, SWEEP_T, smemSweep>>>(pred, out, keep);
}

// round 7
// speedup vs baseline: 8.7703x; 1.0526x over previous
#include <cuda_runtime.h>
#include <stdint.h>

#define NPRED    25200
#define PRED_C   9
#define TOPK     1000
#define CONF_T   0.7f
#define IOU_T    0.45f
#define MASKW    32
#define BMAX     32

#define NSLICE   25
#define ROWS_SL  1008
#define FILT_T   256

#define CANDCAP  4096
#define SEL_N    1024
#define SORT_T   1024

#define MSLICES  16
#define MASK_T   256
#define NWARPS_M (MSLICES * (MASK_T / 32))    // 128 warps per image
#define TASKS    16872                        // sum_w min(1000, 32w+32)

#define SWEEP_T  512

typedef unsigned long long u64;
typedef unsigned int u32;

// ---------------- global scratch ----------------
__device__ int    g_cnt [BMAX * NSLICE];
__device__ u64    g_cand[BMAX * NSLICE * ROWS_SL];
__device__ float4 g_box [BMAX * 1024];
__device__ float  g_score[BMAX * 1024];
__device__ float  g_area[BMAX * 1024];
__device__ int    g_idx [BMAX * 1024];
__device__ u32    g_mask[BMAX * TOPK * MASKW];   // lower-triangle words never written (stay 0)

// ============================================================
// 1) filter: full-chip pass over predictions
// ============================================================
__global__ __launch_bounds__(FILT_T)
void k_filter(const float* __restrict__ pred)
{
    __shared__ u64 buf[ROWS_SL];
    __shared__ int cnt;

    const int img   = blockIdx.x;
    const int slice = blockIdx.y;
    const int tid   = threadIdx.x;
    const float* p  = pred + (size_t)img * NPRED * PRED_C;

    if (tid == 0) cnt = 0;
    __syncthreads();

    const int base = slice * ROWS_SL;
    #pragma unroll
    for (int r = 0; r < 4; r++) {
        int row = tid + r * FILT_T;
        if (row < ROWS_SL) {
            int i = base + row;
            float obj = p[i * PRED_C + 4];
            float cls = p[i * PRED_C + 5];
            float conf = __fmul_rn(obj, cls);
            if (obj > CONF_T && conf > CONF_T) {
                int pos = atomicAdd(&cnt, 1);
                buf[pos] = ((u64)__float_as_uint(conf) << 32) |
                           (u64)(0xFFFFFFFFu - (u32)i);
            }
        }
    }
    __syncthreads();

    int n = cnt;
    if (tid == 0) g_cnt[img * NSLICE + slice] = n;
    u64* dst = g_cand + (size_t)(img * NSLICE + slice) * ROWS_SL;
    for (int k = tid; k < n; k += FILT_T) dst[k] = buf[k];
}

// ============================================================
// 2) sort: gather, hierarchical-scan select, double-buffered bitonic
// ============================================================
__global__ __launch_bounds__(SORT_T, 1)
void k_sort(const float* __restrict__ pred)
{
    extern __shared__ unsigned char sraw[];
    u64* skey  = (u64*)sraw;                          // CANDCAP
    u64* skey2 = skey + CANDCAP;                      // SEL_N (buffer A)
    u64* skey3 = skey2 + SEL_N;                       // SEL_N (buffer B)
    u32* hist  = (u32*)(skey3 + SEL_N);               // 1024
    u32* wsum  = hist + 1024;                         // 32
    u32* woff  = wsum + 32;                           // 32
    int* spfx  = (int*)(woff + 32);                   // 33
    int* misc  = spfx + 33;                           // [0]=total [1]=T [2]=kept

    const int img = blockIdx.x;
    const int tid = threadIdx.x;
    const int lane = tid & 31, warp = tid >> 5;
    const float* p = pred + (size_t)img * NPRED * PRED_C;

    // prefix over slice counts (warp 0)
    if (tid < 32) {
        int c = (tid < NSLICE) ? g_cnt[img * NSLICE + tid] : 0;
        int x = c;
        #pragma unroll
        for (int d = 1; d < 32; d <<= 1) {
            int y = __shfl_up_sync(0xFFFFFFFFu, x, d);
            if ((tid & 31) >= d) x += y;
        }
        spfx[tid + 1] = x;
        if (tid == 0) spfx[0] = 0;
        if (tid == 31) misc[0] = x;
    }
    __syncthreads();

    int total = misc[0];
    if (total > CANDCAP) total = CANDCAP;

    // gather candidate keys
    for (int s = 0; s < NSLICE; s++) {
        int b0 = spfx[s], b1 = spfx[s + 1];
        const u64* src = g_cand + (size_t)(img * NSLICE + s) * ROWS_SL;
        for (int k = b0 + tid; k < b1; k += SORT_T)
            if (k < CANDCAP) skey[k] = src[k - b0];
    }
    for (int k = total + tid; k < CANDCAP; k += SORT_T) skey[k] = 0ull;
    hist[tid] = 0;
    __syncthreads();

    // histogram of conf bits (monotonic bins)
    for (int k = tid; k < total; k += SORT_T) {
        u32 bits = (u32)(skey[k] >> 32);
        int b = (int)((bits - 0x3F000000u) >> 13);
        b = b < 0 ? 0 : (b > 1023 ? 1023 : b);
        atomicAdd(&hist[b], 1u);
    }
    __syncthreads();

    // hierarchical suffix sums (shfl within warp, warp0 combines)
    {
        u32 x = hist[tid];
        #pragma unroll
        for (int d = 1; d < 32; d <<= 1) {
            u32 y = __shfl_down_sync(0xFFFFFFFFu, x, d);
            if (lane + d < 32) x += y;
        }
        if (lane == 0) wsum[warp] = x;   // warp total
        __syncthreads();
        if (warp == 0) {
            u32 t = wsum[lane];
            u32 sx = t;
            #pragma unroll
            for (int d = 1; d < 32; d <<= 1) {
                u32 y = __shfl_down_sync(0xFFFFFFFFu, sx, d);
                if (lane + d < 32) sx += y;
            }
            woff[lane] = sx - t;         // exclusive suffix over warps
        }
        __syncthreads();
        hist[tid] = x + woff[warp];      // inclusive suffix from bin tid
        __syncthreads();
    }

    int need = total < TOPK ? total : TOPK;
    if ((int)hist[tid] >= need && (tid == 1023 || (int)hist[tid + 1] < need))
        misc[1] = tid;
    if (tid == 0) misc[2] = 0;
    __syncthreads();

    int T = misc[1];
    int kept = (int)hist[T];
    bool fallback = (kept > SEL_N);

    u64 mykey;
    if (!fallback) {
        for (int k = tid; k < total; k += SORT_T) {
            u64 key = skey[k];
            u32 bits = (u32)(key >> 32);
            int b = (int)((bits - 0x3F000000u) >> 13);
            b = b < 0 ? 0 : (b > 1023 ? 1023 : b);
            if (b >= T) {
                int pos = atomicAdd(&misc[2], 1);
                skey2[pos] = key;
            }
        }
        __syncthreads();
        for (int k = kept + tid; k < SEL_N; k += SORT_T) skey2[k] = 0ull;
        __syncthreads();

        // ---- double-buffered hybrid bitonic: 1 elem/thread ----
        u64 v = skey2[tid];
        #pragma unroll
        for (int k = 2; k <= 32; k <<= 1) {
            #pragma unroll
            for (int j = k >> 1; j > 0; j >>= 1) {
                u64 o = __shfl_xor_sync(0xFFFFFFFFu, v, j);
                bool keep_max = ((tid & j) == 0) == ((tid & k) == 0);
                bool vbig = v > o;
                v = (keep_max == vbig) ? v : o;
            }
        }
        u64* bufs[2] = { skey2, skey3 };
        int cur = 0;
        bufs[cur][tid] = v;             // establish invariant
        __syncthreads();
        #pragma unroll
        for (int k = 64; k <= SEL_N; k <<= 1) {
            for (int j = k >> 1; j >= 32; j >>= 1) {
                u64 o = bufs[cur][tid ^ j];
                bool keep_max = ((tid & j) == 0) == ((tid & k) == 0);
                bool vbig = v > o;
                v = (keep_max == vbig) ? v : o;
                bufs[cur ^ 1][tid] = v;
                cur ^= 1;
                __syncthreads();
            }
            #pragma unroll
            for (int j = 16; j > 0; j >>= 1) {
                u64 o = __shfl_xor_sync(0xFFFFFFFFu, v, j);
                bool keep_max = ((tid & j) == 0) == ((tid & k) == 0);
                bool vbig = v > o;
                v = (keep_max == vbig) ? v : o;
            }
            if (k < SEL_N) {            // refresh invariant for next k's smem step
                bufs[cur][tid] = v;
                __syncthreads();
            }
        }
        mykey = v;                      // thread tid holds sorted[tid]
    } else {
        u64* sbuf = skey;
        const int n = CANDCAP;
        __syncthreads();
        for (int k = 2; k <= n; k <<= 1) {
            for (int j = k >> 1; j > 0; j >>= 1) {
                for (int q = 0; q < n; q += SORT_T) {
                    int i = tid + q;
                    int ixj = i ^ j;
                    if (ixj > i) {
                        u64 a = sbuf[i], b = sbuf[ixj];
                        if (((i & k) == 0) ? (a < b) : (a > b)) {
                            sbuf[i] = b; sbuf[ixj] = a;
                        }
                    }
                }
                __syncthreads();
            }
        }
        mykey = sbuf[tid];
    }

    // extract top-1000
    if (tid < TOPK) {
        u64 key = mykey;
        float4 b; float sc, ar; int idx;
        if ((key >> 32) != 0ull) {
            idx = (int)(0xFFFFFFFFu - (u32)(key & 0xFFFFFFFFull));
            sc  = __uint_as_float((u32)(key >> 32));
            float x = p[idx * PRED_C + 0];
            float y = p[idx * PRED_C + 1];
            float w = p[idx * PRED_C + 2];
            float h = p[idx * PRED_C + 3];
            float hw = __fmul_rn(w, 0.5f);
            float hh = __fmul_rn(h, 0.5f);
            b = make_float4(__fsub_rn(x, hw), __fsub_rn(y, hh),
                            __fadd_rn(x, hw), __fadd_rn(y, hh));
            ar = __fmul_rn(__fsub_rn(b.z, b.x), __fsub_rn(b.w, b.y));
        } else {
            idx = -1; sc = -1.0f; ar = 0.0f;
            b = make_float4(0.f, 0.f, 0.f, 0.f);
        }
        g_box  [img * 1024 + tid] = b;
        g_score[img * 1024 + tid] = sc;
        g_area [img * 1024 + tid] = ar;
        g_idx  [img * 1024 + tid] = idx;
    }
}

// ============================================================
// 3) mask: balanced upper-triangle (row, word) tasks, ballot per word
// ============================================================
__global__ __launch_bounds__(MASK_T)
void k_mask()
{
    __shared__ float4 sbox[TOPK];
    __shared__ float  sarea[TOPK];

    const int img  = blockIdx.x;
    const int tid  = threadIdx.x;
    const int lane = tid & 31;
    const int gw   = blockIdx.y * (MASK_T / 32) + (tid >> 5);

    for (int i = tid; i < TOPK; i += MASK_T) {
        sbox[i]  = g_box [img * 1024 + i];
        sarea[i] = g_area[img * 1024 + i];
    }
    __syncthreads();

    u32* gm = g_mask + (size_t)img * TOPK * MASKW;

    int u    = (int)(((long long)gw * TASKS) / NWARPS_M);
    int uend = (int)(((long long)(gw + 1) * TASKS) / NWARPS_M);

    int w = 0, acc = 0;
    while (true) {
        int cw = 32 * w + 32; if (cw > TOPK) cw = TOPK;
        if (acc + cw > u) break;
        acc += cw; w++;
    }
    int i  = u - acc;
    int cw = 32 * w + 32; if (cw > TOPK) cw = TOPK;

    int j = w * 32 + lane;
    bool jv = (j < TOPK);
    float4 bj = sbox[jv ? j : 0];
    float  aj = sarea[jv ? j : 0];

    for (; u < uend; ++u) {
        if (i == cw) {
            w++; i = 0;
            cw = 32 * w + 32; if (cw > TOPK) cw = TOPK;
            j = w * 32 + lane;
            jv = (j < TOPK);
            bj = sbox[jv ? j : 0];
            aj = sarea[jv ? j : 0];
        }
        float4 bi = sbox[i];
        float  ai = sarea[i];
        float lx = fmaxf(bi.x, bj.x);
        float ly = fmaxf(bi.y, bj.y);
        float rx = fminf(bi.z, bj.z);
        float ry = fminf(bi.w, bj.w);
        float iw = fmaxf(__fsub_rn(rx, lx), 0.0f);
        float ih = fmaxf(__fsub_rn(ry, ly), 0.0f);
        float inter = __fmul_rn(iw, ih);
        bool sup = false;
        if (j > i && jv && inter > 0.0f) {
            float denom = __fadd_rn(__fsub_rn(__fadd_rn(ai, aj), inter), 1e-7f);
            sup = (__fdiv_rn(inter, denom) > IOU_T);
        }
        u32 word = __ballot_sync(0xFFFFFFFFu, sup);
        if (lane == 0) gm[i * MASKW + w] = word;
        i++;
    }
}

// ============================================================
// 4) sweep: pipelined resolve/accumulate, 1 barrier per chunk
// ============================================================
#define STEP(b, d) { u32 s = (u32)((int)(alive << (31 - (b))) >> 31); \
                     alive &= ~((d) & s); }

__global__ __launch_bounds__(SWEEP_T, 1)
void k_sweep(const float* __restrict__ pred,
             float* __restrict__ out,
             float* __restrict__ keep_out)
{
    extern __shared__ unsigned char sraw[];
    u32* smask  = (u32*)sraw;                 // 1024*32 (pad rows zeroed)
    u32* sdiag  = smask + 1024 * MASKW;       // 1024 (per-chunk diagonal block)
    u32* ssup   = sdiag + 1024;               // 1024 (chunk w -> word w+1 block)
    u32* svalid = ssup + 1024;                // 32
    u32* skeep  = svalid + 32;                // 32
    u32* sremv  = skeep + 32;                 // 32 (lazily accumulated)

    const int img  = blockIdx.x;
    const int tid  = threadIdx.x;
    const int warp = tid >> 5, lane = tid & 31;

    // mask fill (L2-resident), vectorized; zero pad rows 1000..1023
    {
        const uint4* src = (const uint4*)(g_mask + (size_t)img * TOPK * MASKW);
        uint4* dst = (uint4*)smask;
        for (int k = tid; k < TOPK * MASKW / 4; k += SWEEP_T) dst[k] = src[k];
        for (int k = TOPK * MASKW + tid; k < 1024 * MASKW; k += SWEEP_T) smask[k] = 0;
    }

    // validity ballots
    for (int k = 0; k < 1024; k += SWEEP_T) {
        int t = k + tid;
        float sc = (t < TOPK) ? g_score[img * 1024 + t] : -1.0f;
        u32 vb = __ballot_sync(0xFFFFFFFFu, sc > CONF_T);
        if (lane == 0) svalid[t >> 5] = vb;
    }
    if (tid < 32) sremv[tid] = 0;
    __syncthreads();

    // contiguous diag + superdiag extraction
    for (int t = tid; t < 1024; t += SWEEP_T) {
        int c = t >> 5;
        sdiag[t] = smask[t * 32 + c];
        ssup[t]  = (c + 1 < 32) ? smask[t * 32 + c + 1] : 0u;
    }
    __syncthreads();

    u32 carry = 0;   // warp0-uniform: chunk w-1's suppression into word w
    for (int w = 0; w < 32; w++) {
        if (warp == 0) {
            // ---- serial resolve of chunk w ----
            const uint4* dq = (const uint4*)(sdiag + w * 32);
            uint4 q0 = dq[0], q1 = dq[1], q2 = dq[2], q3 = dq[3];
            uint4 q4 = dq[4], q5 = dq[5], q6 = dq[6], q7 = dq[7];
            u32 alive = svalid[w] & ~(sremv[w] | carry);
            STEP( 0, q0.x) STEP( 1, q0.y) STEP( 2, q0.z) STEP( 3, q0.w)
            STEP( 4, q1.x) STEP( 5, q1.y) STEP( 6, q1.z) STEP( 7, q1.w)
            STEP( 8, q2.x) STEP( 9, q2.y) STEP(10, q2.z) STEP(11, q2.w)
            STEP(12, q3.x) STEP(13, q3.y) STEP(14, q3.z) STEP(15, q3.w)
            STEP(16, q4.x) STEP(17, q4.y) STEP(18, q4.z) STEP(19, q4.w)
            STEP(20, q5.x) STEP(21, q5.y) STEP(22, q5.z) STEP(23, q5.w)
            STEP(24, q6.x) STEP(25, q6.y) STEP(26, q6.z) STEP(27, q6.w)
            STEP(28, q7.x) STEP(29, q7.y) STEP(30, q7.z) STEP(31, q7.w)
            if (lane == 0) skeep[w] = alive;
            // carry: chunk w -> word w+1 (lane b masks ssup row b, warp-OR)
            u32 contrib = ssup[w * 32 + lane] & (0u - ((alive >> lane) & 1u));
            carry = __reduce_or_sync(0xFFFFFFFFu, contrib);
        } else if (w > 0) {
            // ---- accumulate chunk w-1's kept rows (overlaps resolve) ----
            u32 a = skeep[w - 1];
            u32 partial = 0;
            for (int b = warp - 1; b < 32; b += 15) {
                if ((a >> b) & 1u)
                    partial |= smask[((w - 1) * 32 + b) * 32 + lane];
            }
            if (partial) atomicOr(&sremv[lane], partial);
        }
        __syncthreads();
    }

    const float* p = pred + (size_t)img * NPRED * PRED_C;
    for (int t = tid; t < TOPK; t += SWEEP_T) {
        bool kp = (skeep[t >> 5] >> (t & 31)) & 1u;
        float o0=0.f,o1=0.f,o2=0.f,o3=0.f,o4=0.f,o6=0.f,o7=0.f,o8=0.f;
        if (kp) {
            float4 b = g_box[img * 1024 + t];
            o0 = b.x; o1 = b.y; o2 = b.z; o3 = b.w;
            o4 = g_score[img * 1024 + t];
            int idx = g_idx[img * 1024 + t];
            o6 = p[idx * PRED_C + 6];
            o7 = p[idx * PRED_C + 7];
            o8 = p[idx * PRED_C + 8];
        }
        float* orow = out + ((size_t)img * TOPK + t) * PRED_C;
        orow[0]=o0; orow[1]=o1; orow[2]=o2; orow[3]=o3;
        orow[4]=o4; orow[5]=0.0f;
        orow[6]=o6; orow[7]=o7; orow[8]=o8;
        keep_out[(size_t)img * TOPK + t] = kp ? 1.0f : 0.0f;
    }
}

extern "C" void kernel_launch(void* const* d_in, const int* in_sizes, int n_in,
                              void* d_out, int out_size)
{
    const float* pred = (const float*)d_in[0];
    int B = in_sizes[0] / (NPRED * PRED_C);

    float* out  = (float*)d_out;
    float* keep = out + (size_t)B * TOPK * PRED_C;

    size_t smemSort  = (size_t)CANDCAP * 8 + (size_t)SEL_N * 8 * 2 +
                       1024 * 4 + 64 * 4 + 80 * 4;
    size_t smemSweep = (size_t)1024 * MASKW * 4 + 2 * 1024 * 4 + 128 * 4;

    static bool attr_set = false;
    if (!attr_set) {
        cudaFuncSetAttribute(k_sort,  cudaFuncAttributeMaxDynamicSharedMemorySize,
                             (int)smemSort);
        cudaFuncSetAttribute(k_sweep, cudaFuncAttributeMaxDynamicSharedMemorySize,
                             (int)smemSweep);
        attr_set = true;
    }

    k_filter<<<dim3(B, NSLICE), FILT_T>>>(pred);
    k_sort<<<B, SORT_T, smemSort>>>(pred);
    k_mask<<<dim3(B, MSLICES), MASK_T>>>();
    k_sweep<<<B, SWEEP_T, smemSweep>>>(pred, out, keep);
}

// round 8
// speedup vs baseline: 8.7949x; 1.0028x over previous
#include <cuda_runtime.h>
#include <stdint.h>

#define NPRED    25200
#define PRED_C   9
#define TOPK     1000
#define CONF_T   0.7f
#define IOU_T    0.45f
#define MASKW    32
#define BMAX     32

#define NSLICE   25
#define ROWS_SL  1008
#define FILT_T   256

#define CANDCAP  4096
#define SEL_N    1024
#define SORT_T   1024

#define MSLICES  16
#define MASK_T   256
#define NWARPS_M (MSLICES * (MASK_T / 32))    // 128 warps per image
#define TASKS    16872                        // sum_w min(1000, 32w+32)

#define SWEEP_T  512

typedef unsigned long long u64;
typedef unsigned int u32;

// ---------------- global scratch ----------------
__device__ int    g_cnt [BMAX * NSLICE];
__device__ u64    g_cand[BMAX * NSLICE * ROWS_SL];
__device__ float4 g_box [BMAX * 1024];
__device__ float  g_score[BMAX * 1024];
__device__ float  g_area[BMAX * 1024];
__device__ int    g_idx [BMAX * 1024];
__device__ u32    g_mask[BMAX * TOPK * MASKW];   // lower-triangle words never written (stay 0)

// ============================================================
// 1) filter: full-chip pass over predictions
// ============================================================
__global__ __launch_bounds__(FILT_T)
void k_filter(const float* __restrict__ pred)
{
    __shared__ u64 buf[ROWS_SL];
    __shared__ int cnt;

    const int img   = blockIdx.x;
    const int slice = blockIdx.y;
    const int tid   = threadIdx.x;
    const float* p  = pred + (size_t)img * NPRED * PRED_C;

    if (tid == 0) cnt = 0;
    __syncthreads();

    const int base = slice * ROWS_SL;
    #pragma unroll
    for (int r = 0; r < 4; r++) {
        int row = tid + r * FILT_T;
        if (row < ROWS_SL) {
            int i = base + row;
            float obj = p[i * PRED_C + 4];
            float cls = p[i * PRED_C + 5];
            float conf = __fmul_rn(obj, cls);
            if (obj > CONF_T && conf > CONF_T) {
                int pos = atomicAdd(&cnt, 1);
                buf[pos] = ((u64)__float_as_uint(conf) << 32) |
                           (u64)(0xFFFFFFFFu - (u32)i);
            }
        }
    }
    __syncthreads();

    int n = cnt;
    if (tid == 0) g_cnt[img * NSLICE + slice] = n;
    u64* dst = g_cand + (size_t)(img * NSLICE + slice) * ROWS_SL;
    for (int k = tid; k < n; k += FILT_T) dst[k] = buf[k];
}

// ============================================================
// 2) sort: gather, hierarchical-scan select, double-buffered bitonic
// ============================================================
__global__ __launch_bounds__(SORT_T, 1)
void k_sort(const float* __restrict__ pred)
{
    extern __shared__ unsigned char sraw[];
    u64* skey  = (u64*)sraw;                          // CANDCAP
    u64* skey2 = skey + CANDCAP;                      // SEL_N (buffer A)
    u64* skey3 = skey2 + SEL_N;                       // SEL_N (buffer B)
    u32* hist  = (u32*)(skey3 + SEL_N);               // 1024
    u32* wsum  = hist + 1024;                         // 32
    u32* woff  = wsum + 32;                           // 32
    int* spfx  = (int*)(woff + 32);                   // 33
    int* misc  = spfx + 33;                           // [0]=total [1]=T [2]=kept

    const int img = blockIdx.x;
    const int tid = threadIdx.x;
    const int lane = tid & 31, warp = tid >> 5;
    const float* p = pred + (size_t)img * NPRED * PRED_C;

    // prefix over slice counts (warp 0)
    if (tid < 32) {
        int c = (tid < NSLICE) ? g_cnt[img * NSLICE + tid] : 0;
        int x = c;
        #pragma unroll
        for (int d = 1; d < 32; d <<= 1) {
            int y = __shfl_up_sync(0xFFFFFFFFu, x, d);
            if ((tid & 31) >= d) x += y;
        }
        spfx[tid + 1] = x;
        if (tid == 0) spfx[0] = 0;
        if (tid == 31) misc[0] = x;
    }
    __syncthreads();

    int total = misc[0];
    if (total > CANDCAP) total = CANDCAP;

    // gather candidate keys
    for (int s = 0; s < NSLICE; s++) {
        int b0 = spfx[s], b1 = spfx[s + 1];
        const u64* src = g_cand + (size_t)(img * NSLICE + s) * ROWS_SL;
        for (int k = b0 + tid; k < b1; k += SORT_T)
            if (k < CANDCAP) skey[k] = src[k - b0];
    }
    for (int k = total + tid; k < CANDCAP; k += SORT_T) skey[k] = 0ull;
    hist[tid] = 0;
    __syncthreads();

    // histogram of conf bits (monotonic bins)
    for (int k = tid; k < total; k += SORT_T) {
        u32 bits = (u32)(skey[k] >> 32);
        int b = (int)((bits - 0x3F000000u) >> 13);
        b = b < 0 ? 0 : (b > 1023 ? 1023 : b);
        atomicAdd(&hist[b], 1u);
    }
    __syncthreads();

    // hierarchical suffix sums (shfl within warp, warp0 combines)
    {
        u32 x = hist[tid];
        #pragma unroll
        for (int d = 1; d < 32; d <<= 1) {
            u32 y = __shfl_down_sync(0xFFFFFFFFu, x, d);
            if (lane + d < 32) x += y;
        }
        if (lane == 0) wsum[warp] = x;   // warp total
        __syncthreads();
        if (warp == 0) {
            u32 t = wsum[lane];
            u32 sx = t;
            #pragma unroll
            for (int d = 1; d < 32; d <<= 1) {
                u32 y = __shfl_down_sync(0xFFFFFFFFu, sx, d);
                if (lane + d < 32) sx += y;
            }
            woff[lane] = sx - t;         // exclusive suffix over warps
        }
        __syncthreads();
        hist[tid] = x + woff[warp];      // inclusive suffix from bin tid
        __syncthreads();
    }

    int need = total < TOPK ? total : TOPK;
    if ((int)hist[tid] >= need && (tid == 1023 || (int)hist[tid + 1] < need))
        misc[1] = tid;
    if (tid == 0) misc[2] = 0;
    __syncthreads();

    int T = misc[1];
    int kept = (int)hist[T];
    bool fallback = (kept > SEL_N);

    u64 mykey;
    if (!fallback) {
        for (int k = tid; k < total; k += SORT_T) {
            u64 key = skey[k];
            u32 bits = (u32)(key >> 32);
            int b = (int)((bits - 0x3F000000u) >> 13);
            b = b < 0 ? 0 : (b > 1023 ? 1023 : b);
            if (b >= T) {
                int pos = atomicAdd(&misc[2], 1);
                skey2[pos] = key;
            }
        }
        __syncthreads();
        for (int k = kept + tid; k < SEL_N; k += SORT_T) skey2[k] = 0ull;
        __syncthreads();

        // ---- double-buffered hybrid bitonic: 1 elem/thread ----
        u64 v = skey2[tid];
        #pragma unroll
        for (int k = 2; k <= 32; k <<= 1) {
            #pragma unroll
            for (int j = k >> 1; j > 0; j >>= 1) {
                u64 o = __shfl_xor_sync(0xFFFFFFFFu, v, j);
                bool keep_max = ((tid & j) == 0) == ((tid & k) == 0);
                bool vbig = v > o;
                v = (keep_max == vbig) ? v : o;
            }
        }
        u64* bufs[2] = { skey2, skey3 };
        int cur = 0;
        bufs[cur][tid] = v;             // establish invariant
        __syncthreads();
        #pragma unroll
        for (int k = 64; k <= SEL_N; k <<= 1) {
            for (int j = k >> 1; j >= 32; j >>= 1) {
                u64 o = bufs[cur][tid ^ j];
                bool keep_max = ((tid & j) == 0) == ((tid & k) == 0);
                bool vbig = v > o;
                v = (keep_max == vbig) ? v : o;
                bufs[cur ^ 1][tid] = v;
                cur ^= 1;
                __syncthreads();
            }
            #pragma unroll
            for (int j = 16; j > 0; j >>= 1) {
                u64 o = __shfl_xor_sync(0xFFFFFFFFu, v, j);
                bool keep_max = ((tid & j) == 0) == ((tid & k) == 0);
                bool vbig = v > o;
                v = (keep_max == vbig) ? v : o;
            }
            if (k < SEL_N) {            // refresh invariant for next k's smem step
                bufs[cur][tid] = v;
                __syncthreads();
            }
        }
        mykey = v;                      // thread tid holds sorted[tid]
    } else {
        u64* sbuf = skey;
        const int n = CANDCAP;
        __syncthreads();
        for (int k = 2; k <= n; k <<= 1) {
            for (int j = k >> 1; j > 0; j >>= 1) {
                for (int q = 0; q < n; q += SORT_T) {
                    int i = tid + q;
                    int ixj = i ^ j;
                    if (ixj > i) {
                        u64 a = sbuf[i], b = sbuf[ixj];
                        if (((i & k) == 0) ? (a < b) : (a > b)) {
                            sbuf[i] = b; sbuf[ixj] = a;
                        }
                    }
                }
                __syncthreads();
            }
        }
        mykey = sbuf[tid];
    }

    // extract top-1000
    if (tid < TOPK) {
        u64 key = mykey;
        float4 b; float sc, ar; int idx;
        if ((key >> 32) != 0ull) {
            idx = (int)(0xFFFFFFFFu - (u32)(key & 0xFFFFFFFFull));
            sc  = __uint_as_float((u32)(key >> 32));
            float x = p[idx * PRED_C + 0];
            float y = p[idx * PRED_C + 1];
            float w = p[idx * PRED_C + 2];
            float h = p[idx * PRED_C + 3];
            float hw = __fmul_rn(w, 0.5f);
            float hh = __fmul_rn(h, 0.5f);
            b = make_float4(__fsub_rn(x, hw), __fsub_rn(y, hh),
                            __fadd_rn(x, hw), __fadd_rn(y, hh));
            ar = __fmul_rn(__fsub_rn(b.z, b.x), __fsub_rn(b.w, b.y));
        } else {
            idx = -1; sc = -1.0f; ar = 0.0f;
            b = make_float4(0.f, 0.f, 0.f, 0.f);
        }
        g_box  [img * 1024 + tid] = b;
        g_score[img * 1024 + tid] = sc;
        g_area [img * 1024 + tid] = ar;
        g_idx  [img * 1024 + tid] = idx;
    }
}

// ============================================================
// 3) mask: balanced upper-triangle (row, word) tasks, ballot per word
// ============================================================
__global__ __launch_bounds__(MASK_T)
void k_mask()
{
    __shared__ float4 sbox[TOPK];
    __shared__ float  sarea[TOPK];

    const int img  = blockIdx.x;
    const int tid  = threadIdx.x;
    const int lane = tid & 31;
    const int gw   = blockIdx.y * (MASK_T / 32) + (tid >> 5);

    for (int i = tid; i < TOPK; i += MASK_T) {
        sbox[i]  = g_box [img * 1024 + i];
        sarea[i] = g_area[img * 1024 + i];
    }
    __syncthreads();

    u32* gm = g_mask + (size_t)img * TOPK * MASKW;

    int u    = (int)(((long long)gw * TASKS) / NWARPS_M);
    int uend = (int)(((long long)(gw + 1) * TASKS) / NWARPS_M);

    int w = 0, acc = 0;
    while (true) {
        int cw = 32 * w + 32; if (cw > TOPK) cw = TOPK;
        if (acc + cw > u) break;
        acc += cw; w++;
    }
    int i  = u - acc;
    int cw = 32 * w + 32; if (cw > TOPK) cw = TOPK;

    int j = w * 32 + lane;
    bool jv = (j < TOPK);
    float4 bj = sbox[jv ? j : 0];
    float  aj = sarea[jv ? j : 0];

    for (; u < uend; ++u) {
        if (i == cw) {
            w++; i = 0;
            cw = 32 * w + 32; if (cw > TOPK) cw = TOPK;
            j = w * 32 + lane;
            jv = (j < TOPK);
            bj = sbox[jv ? j : 0];
            aj = sarea[jv ? j : 0];
        }
        float4 bi = sbox[i];
        float  ai = sarea[i];
        float lx = fmaxf(bi.x, bj.x);
        float ly = fmaxf(bi.y, bj.y);
        float rx = fminf(bi.z, bj.z);
        float ry = fminf(bi.w, bj.w);
        float iw = fmaxf(__fsub_rn(rx, lx), 0.0f);
        float ih = fmaxf(__fsub_rn(ry, ly), 0.0f);
        float inter = __fmul_rn(iw, ih);
        bool sup = false;
        if (j > i && jv && inter > 0.0f) {
            float denom = __fadd_rn(__fsub_rn(__fadd_rn(ai, aj), inter), 1e-7f);
            sup = (__fdiv_rn(inter, denom) > IOU_T);
        }
        u32 word = __ballot_sync(0xFFFFFFFFu, sup);
        if (lane == 0) gm[i * MASKW + w] = word;
        i++;
    }
}

// ============================================================
// 4) sweep: pipelined resolve/accumulate, 1 barrier per chunk
// ============================================================
#define STEP(b, d) { u32 s = (u32)((int)(alive << (31 - (b))) >> 31); \
                     alive &= ~((d) & s); }

__global__ __launch_bounds__(SWEEP_T, 1)
void k_sweep(const float* __restrict__ pred,
             float* __restrict__ out,
             float* __restrict__ keep_out)
{
    extern __shared__ unsigned char sraw[];
    u32* smask  = (u32*)sraw;                 // 1024*32 (pad rows zeroed)
    u32* sdiag  = smask + 1024 * MASKW;       // 1024 (per-chunk diagonal block)
    u32* ssup   = sdiag + 1024;               // 1024 (chunk w -> word w+1 block)
    u32* svalid = ssup + 1024;                // 32
    u32* skeep  = svalid + 32;                // 32
    u32* sremv  = skeep + 32;                 // 32 (lazily accumulated)

    const int img  = blockIdx.x;
    const int tid  = threadIdx.x;
    const int warp = tid >> 5, lane = tid & 31;

    // mask fill (L2-resident), vectorized; zero pad rows 1000..1023
    {
        const uint4* src = (const uint4*)(g_mask + (size_t)img * TOPK * MASKW);
        uint4* dst = (uint4*)smask;
        for (int k = tid; k < TOPK * MASKW / 4; k += SWEEP_T) dst[k] = src[k];
        for (int k = TOPK * MASKW + tid; k < 1024 * MASKW; k += SWEEP_T) smask[k] = 0;
    }

    // validity ballots
    for (int k = 0; k < 1024; k += SWEEP_T) {
        int t = k + tid;
        float sc = (t < TOPK) ? g_score[img * 1024 + t] : -1.0f;
        u32 vb = __ballot_sync(0xFFFFFFFFu, sc > CONF_T);
        if (lane == 0) svalid[t >> 5] = vb;
    }
    if (tid < 32) sremv[tid] = 0;
    __syncthreads();

    // contiguous diag + superdiag extraction
    for (int t = tid; t < 1024; t += SWEEP_T) {
        int c = t >> 5;
        sdiag[t] = smask[t * 32 + c];
        ssup[t]  = (c + 1 < 32) ? smask[t * 32 + c + 1] : 0u;
    }
    __syncthreads();

    u32 carry = 0;   // warp0-uniform: chunk w-1's suppression into word w
    for (int w = 0; w < 32; w++) {
        if (warp == 0) {
            // ---- serial resolve of chunk w ----
            const uint4* dq = (const uint4*)(sdiag + w * 32);
            uint4 q0 = dq[0], q1 = dq[1], q2 = dq[2], q3 = dq[3];
            uint4 q4 = dq[4], q5 = dq[5], q6 = dq[6], q7 = dq[7];
            u32 alive = svalid[w] & ~(sremv[w] | carry);
            STEP( 0, q0.x) STEP( 1, q0.y) STEP( 2, q0.z) STEP( 3, q0.w)
            STEP( 4, q1.x) STEP( 5, q1.y) STEP( 6, q1.z) STEP( 7, q1.w)
            STEP( 8, q2.x) STEP( 9, q2.y) STEP(10, q2.z) STEP(11, q2.w)
            STEP(12, q3.x) STEP(13, q3.y) STEP(14, q3.z) STEP(15, q3.w)
            STEP(16, q4.x) STEP(17, q4.y) STEP(18, q4.z) STEP(19, q4.w)
            STEP(20, q5.x) STEP(21, q5.y) STEP(22, q5.z) STEP(23, q5.w)
            STEP(24, q6.x) STEP(25, q6.y) STEP(26, q6.z) STEP(27, q6.w)
            STEP(28, q7.x) STEP(29, q7.y) STEP(30, q7.z) STEP(31, q7.w)
            if (lane == 0) skeep[w] = alive;
            // carry: chunk w -> word w+1 (lane b masks ssup row b, warp-OR)
            u32 contrib = ssup[w * 32 + lane] & (0u - ((alive >> lane) & 1u));
            carry = __reduce_or_sync(0xFFFFFFFFu, contrib);
        } else if (w > 0) {
            // ---- accumulate chunk w-1's kept rows (overlaps resolve) ----
            u32 a = skeep[w - 1];
            u32 partial = 0;
            for (int b = warp - 1; b < 32; b += 15) {
                if ((a >> b) & 1u)
                    partial |= smask[((w - 1) * 32 + b) * 32 + lane];
            }
            if (partial) atomicOr(&sremv[lane], partial);
        }
        __syncthreads();
    }

    const float* p = pred + (size_t)img * NPRED * PRED_C;
    for (int t = tid; t < TOPK; t += SWEEP_T) {
        bool kp = (skeep[t >> 5] >> (t & 31)) & 1u;
        float o0=0.f,o1=0.f,o2=0.f,o3=0.f,o4=0.f,o6=0.f,o7=0.f,o8=0.f;
        if (kp) {
            float4 b = g_box[img * 1024 + t];
            o0 = b.x; o1 = b.y; o2 = b.z; o3 = b.w;
            o4 = g_score[img * 1024 + t];
            int idx = g_idx[img * 1024 + t];
            o6 = p[idx * PRED_C + 6];
            o7 = p[idx * PRED_C + 7];
            o8 = p[idx * PRED_C + 8];
        }
        float* orow = out + ((size_t)img * TOPK + t) * PRED_C;
        orow[0]=o0; orow[1]=o1; orow[2]=o2; orow[3]=o3;
        orow[4]=o4; orow[5]=0.0f;
        orow[6]=o6; orow[7]=o7; orow[8]=o8;
        keep_out[(size_t)img * TOPK + t] = kp ? 1.0f : 0.0f;
    }
}

extern "C" void kernel_launch(void* const* d_in, const int* in_sizes, int n_in,
                              void* d_out, int out_size)
{
    const float* pred = (const float*)d_in[0];
    int B = in_sizes[0] / (NPRED * PRED_C);

    float* out  = (float*)d_out;
    float* keep = out + (size_t)B * TOPK * PRED_C;

    size_t smemSort  = (size_t)CANDCAP * 8 + (size_t)SEL_N * 8 * 2 +
                       1024 * 4 + 64 * 4 + 80 * 4;
    size_t smemSweep = (size_t)1024 * MASKW * 4 + 2 * 1024 * 4 + 128 * 4;

    static bool attr_set = false;
    if (!attr_set) {
        cudaFuncSetAttribute(k_sort,  cudaFuncAttributeMaxDynamicSharedMemorySize,
                             (int)smemSort);
        cudaFuncSetAttribute(k_sweep, cudaFuncAttributeMaxDynamicSharedMemorySize,
                             (int)smemSweep);
        attr_set = true;
    }

    k_filter<<<dim3(B, NSLICE), FILT_T>>>(pred);
    k_sort<<<B, SORT_T, smemSort>>>(pred);
    k_mask<<<dim3(B, MSLICES), MASK_T>>>();
    k_sweep<<<B, SWEEP_T, smemSweep>>>(pred, out, keep);
}

// round 9
// speedup vs baseline: 9.4485x; 1.0743x over previous
#include <cuda_runtime.h>
#include <stdint.h>

#define NPRED    25200
#define PRED_C   9
#define TOPK     1000
#define CONF_T   0.7f
#define IOU_T    0.45f
#define MASKW    32
#define BMAX     32

#define NSLICE   25
#define ROWS_SL  1008
#define FILT_T   256

#define CANDCAP  4096
#define SEL_N    1024
#define SORT_T   1024

#define MSLICES  16
#define MASK_T   256
#define NWARPS_M (MSLICES * (MASK_T / 32))    // 128 warps per image
#define TASKS    16872                        // sum_w min(1000, 32w+32)

#define SWEEP_T  512

typedef unsigned long long u64;
typedef unsigned int u32;

// ---------------- global scratch ----------------
__device__ int    g_cnt [BMAX * NSLICE];
__device__ u64    g_cand[BMAX * NSLICE * ROWS_SL];
__device__ float4 g_box [BMAX * 1024];
__device__ float  g_score[BMAX * 1024];
__device__ float  g_area[BMAX * 1024];
__device__ int    g_idx [BMAX * 1024];
__device__ u32    g_mask[BMAX * TOPK * MASKW];   // lower-triangle words never written (stay 0)

// ============================================================
// 1) filter: full-chip pass over predictions
// ============================================================
__global__ __launch_bounds__(FILT_T)
void k_filter(const float* __restrict__ pred)
{
    __shared__ u64 buf[ROWS_SL];
    __shared__ int cnt;

    const int img   = blockIdx.x;
    const int slice = blockIdx.y;
    const int tid   = threadIdx.x;
    const float* p  = pred + (size_t)img * NPRED * PRED_C;

    if (tid == 0) cnt = 0;
    __syncthreads();

    const int base = slice * ROWS_SL;
    #pragma unroll
    for (int r = 0; r < 4; r++) {
        int row = tid + r * FILT_T;
        if (row < ROWS_SL) {
            int i = base + row;
            float obj = p[i * PRED_C + 4];
            float cls = p[i * PRED_C + 5];
            float conf = __fmul_rn(obj, cls);
            if (obj > CONF_T && conf > CONF_T) {
                int pos = atomicAdd(&cnt, 1);
                buf[pos] = ((u64)__float_as_uint(conf) << 32) |
                           (u64)(0xFFFFFFFFu - (u32)i);
            }
        }
    }
    __syncthreads();

    int n = cnt;
    if (tid == 0) g_cnt[img * NSLICE + slice] = n;
    u64* dst = g_cand + (size_t)(img * NSLICE + slice) * ROWS_SL;
    for (int k = tid; k < n; k += FILT_T) dst[k] = buf[k];
}

// ============================================================
// 2) sort: parallel gather (binary search), histogram select,
//    warp-aggregated extraction, double-buffered bitonic
// ============================================================
__global__ __launch_bounds__(SORT_T, 1)
void k_sort(const float* __restrict__ pred)
{
    extern __shared__ unsigned char sraw[];
    u64* skey  = (u64*)sraw;                          // CANDCAP
    u64* skey2 = skey + CANDCAP;                      // SEL_N (buffer A)
    u64* skey3 = skey2 + SEL_N;                       // SEL_N (buffer B)
    u32* hist  = (u32*)(skey3 + SEL_N);               // 1024
    u32* wsum  = hist + 1024;                         // 32
    u32* woff  = wsum + 32;                           // 32
    int* spfx  = (int*)(woff + 32);                   // 33
    int* misc  = spfx + 33;                           // [0]=total [1]=T [2]=kept

    const int img = blockIdx.x;
    const int tid = threadIdx.x;
    const int lane = tid & 31, warp = tid >> 5;
    const float* p = pred + (size_t)img * NPRED * PRED_C;

    // prefix over slice counts (warp 0)
    if (tid < 32) {
        int c = (tid < NSLICE) ? g_cnt[img * NSLICE + tid] : 0;
        int x = c;
        #pragma unroll
        for (int d = 1; d < 32; d <<= 1) {
            int y = __shfl_up_sync(0xFFFFFFFFu, x, d);
            if ((tid & 31) >= d) x += y;
        }
        spfx[tid + 1] = x;
        if (tid == 0) spfx[0] = 0;
        if (tid == 31) misc[0] = x;
    }
    __syncthreads();

    int total = misc[0];
    if (total > CANDCAP) total = CANDCAP;

    // ---- parallel gather: thread k binary-searches its slice ----
    for (int k = tid; k < total; k += SORT_T) {
        int lo = 0, hi = NSLICE;             // invariant spfx[lo] <= k < spfx[hi]
        #pragma unroll
        for (int it = 0; it < 5; it++) {     // ceil(log2(25)) = 5
            int mid = (lo + hi) >> 1;
            if (spfx[mid] <= k) lo = mid; else hi = mid;
        }
        skey[k] = g_cand[(size_t)(img * NSLICE + lo) * ROWS_SL + (k - spfx[lo])];
    }
    for (int k = total + tid; k < CANDCAP; k += SORT_T) skey[k] = 0ull;
    hist[tid] = 0;
    __syncthreads();

    // histogram of conf bits (monotonic bins)
    for (int k = tid; k < total; k += SORT_T) {
        u32 bits = (u32)(skey[k] >> 32);
        int b = (int)((bits - 0x3F000000u) >> 13);
        b = b < 0 ? 0 : (b > 1023 ? 1023 : b);
        atomicAdd(&hist[b], 1u);
    }
    __syncthreads();

    // hierarchical suffix sums (shfl within warp, warp0 combines)
    {
        u32 x = hist[tid];
        #pragma unroll
        for (int d = 1; d < 32; d <<= 1) {
            u32 y = __shfl_down_sync(0xFFFFFFFFu, x, d);
            if (lane + d < 32) x += y;
        }
        if (lane == 0) wsum[warp] = x;
        __syncthreads();
        if (warp == 0) {
            u32 t = wsum[lane];
            u32 sx = t;
            #pragma unroll
            for (int d = 1; d < 32; d <<= 1) {
                u32 y = __shfl_down_sync(0xFFFFFFFFu, sx, d);
                if (lane + d < 32) sx += y;
            }
            woff[lane] = sx - t;
        }
        __syncthreads();
        hist[tid] = x + woff[warp];
        __syncthreads();
    }

    int need = total < TOPK ? total : TOPK;
    if ((int)hist[tid] >= need && (tid == 1023 || (int)hist[tid + 1] < need))
        misc[1] = tid;
    if (tid == 0) misc[2] = 0;
    __syncthreads();

    int T = misc[1];
    int kept = (int)hist[T];
    bool fallback = (kept > SEL_N);

    u64 mykey;
    if (!fallback) {
        // warp-aggregated compaction
        for (int k = tid; k < CANDCAP; k += SORT_T) {
            bool take = false;
            u64 key = 0ull;
            if (k < total) {
                key = skey[k];
                u32 bits = (u32)(key >> 32);
                int b = (int)((bits - 0x3F000000u) >> 13);
                b = b < 0 ? 0 : (b > 1023 ? 1023 : b);
                take = (b >= T);
            }
            u32 bal = __ballot_sync(0xFFFFFFFFu, take);
            if (bal) {
                int nset = __popc(bal);
                int base_pos;
                if (lane == __ffs(bal) - 1)
                    base_pos = atomicAdd(&misc[2], nset);
                base_pos = __shfl_sync(0xFFFFFFFFu, base_pos, __ffs(bal) - 1);
                if (take) {
                    int off = __popc(bal & ((1u << lane) - 1u));
                    skey2[base_pos + off] = key;
                }
            }
        }
        __syncthreads();
        for (int k = kept + tid; k < SEL_N; k += SORT_T) skey2[k] = 0ull;
        __syncthreads();

        // ---- double-buffered hybrid bitonic: 1 elem/thread ----
        u64 v = skey2[tid];
        #pragma unroll
        for (int k = 2; k <= 32; k <<= 1) {
            #pragma unroll
            for (int j = k >> 1; j > 0; j >>= 1) {
                u64 o = __shfl_xor_sync(0xFFFFFFFFu, v, j);
                bool keep_max = ((tid & j) == 0) == ((tid & k) == 0);
                bool vbig = v > o;
                v = (keep_max == vbig) ? v : o;
            }
        }
        u64* bufs[2] = { skey2, skey3 };
        int cur = 0;
        bufs[cur][tid] = v;
        __syncthreads();
        #pragma unroll
        for (int k = 64; k <= SEL_N; k <<= 1) {
            for (int j = k >> 1; j >= 32; j >>= 1) {
                u64 o = bufs[cur][tid ^ j];
                bool keep_max = ((tid & j) == 0) == ((tid & k) == 0);
                bool vbig = v > o;
                v = (keep_max == vbig) ? v : o;
                bufs[cur ^ 1][tid] = v;
                cur ^= 1;
                __syncthreads();
            }
            #pragma unroll
            for (int j = 16; j > 0; j >>= 1) {
                u64 o = __shfl_xor_sync(0xFFFFFFFFu, v, j);
                bool keep_max = ((tid & j) == 0) == ((tid & k) == 0);
                bool vbig = v > o;
                v = (keep_max == vbig) ? v : o;
            }
            if (k < SEL_N) {
                bufs[cur][tid] = v;
                __syncthreads();
            }
        }
        mykey = v;
    } else {
        u64* sbuf = skey;
        const int n = CANDCAP;
        __syncthreads();
        for (int k = 2; k <= n; k <<= 1) {
            for (int j = k >> 1; j > 0; j >>= 1) {
                for (int q = 0; q < n; q += SORT_T) {
                    int i = tid + q;
                    int ixj = i ^ j;
                    if (ixj > i) {
                        u64 a = sbuf[i], b = sbuf[ixj];
                        if (((i & k) == 0) ? (a < b) : (a > b)) {
                            sbuf[i] = b; sbuf[ixj] = a;
                        }
                    }
                }
                __syncthreads();
            }
        }
        mykey = sbuf[tid];
    }

    // extract top-1000
    if (tid < TOPK) {
        u64 key = mykey;
        float4 b; float sc, ar; int idx;
        if ((key >> 32) != 0ull) {
            idx = (int)(0xFFFFFFFFu - (u32)(key & 0xFFFFFFFFull));
            sc  = __uint_as_float((u32)(key >> 32));
            float x = p[idx * PRED_C + 0];
            float y = p[idx * PRED_C + 1];
            float w = p[idx * PRED_C + 2];
            float h = p[idx * PRED_C + 3];
            float hw = __fmul_rn(w, 0.5f);
            float hh = __fmul_rn(h, 0.5f);
            b = make_float4(__fsub_rn(x, hw), __fsub_rn(y, hh),
                            __fadd_rn(x, hw), __fadd_rn(y, hh));
            ar = __fmul_rn(__fsub_rn(b.z, b.x), __fsub_rn(b.w, b.y));
        } else {
            idx = -1; sc = -1.0f; ar = 0.0f;
            b = make_float4(0.f, 0.f, 0.f, 0.f);
        }
        g_box  [img * 1024 + tid] = b;
        g_score[img * 1024 + tid] = sc;
        g_area [img * 1024 + tid] = ar;
        g_idx  [img * 1024 + tid] = idx;
    }
}

// ============================================================
// 3) mask: balanced upper-triangle (row, word) tasks, ballot per word
// ============================================================
__global__ __launch_bounds__(MASK_T)
void k_mask()
{
    __shared__ float4 sbox[TOPK];
    __shared__ float  sarea[TOPK];

    const int img  = blockIdx.x;
    const int tid  = threadIdx.x;
    const int lane = tid & 31;
    const int gw   = blockIdx.y * (MASK_T / 32) + (tid >> 5);

    for (int i = tid; i < TOPK; i += MASK_T) {
        sbox[i]  = g_box [img * 1024 + i];
        sarea[i] = g_area[img * 1024 + i];
    }
    __syncthreads();

    u32* gm = g_mask + (size_t)img * TOPK * MASKW;

    int u    = (int)(((long long)gw * TASKS) / NWARPS_M);
    int uend = (int)(((long long)(gw + 1) * TASKS) / NWARPS_M);

    int w = 0, acc = 0;
    while (true) {
        int cw = 32 * w + 32; if (cw > TOPK) cw = TOPK;
        if (acc + cw > u) break;
        acc += cw; w++;
    }
    int i  = u - acc;
    int cw = 32 * w + 32; if (cw > TOPK) cw = TOPK;

    int j = w * 32 + lane;
    bool jv = (j < TOPK);
    float4 bj = sbox[jv ? j : 0];
    float  aj = sarea[jv ? j : 0];

    for (; u < uend; ++u) {
        if (i == cw) {
            w++; i = 0;
            cw = 32 * w + 32; if (cw > TOPK) cw = TOPK;
            j = w * 32 + lane;
            jv = (j < TOPK);
            bj = sbox[jv ? j : 0];
            aj = sarea[jv ? j : 0];
        }
        float4 bi = sbox[i];
        float  ai = sarea[i];
        float lx = fmaxf(bi.x, bj.x);
        float ly = fmaxf(bi.y, bj.y);
        float rx = fminf(bi.z, bj.z);
        float ry = fminf(bi.w, bj.w);
        float iw = fmaxf(__fsub_rn(rx, lx), 0.0f);
        float ih = fmaxf(__fsub_rn(ry, ly), 0.0f);
        float inter = __fmul_rn(iw, ih);
        bool sup = false;
        if (j > i && jv && inter > 0.0f) {
            float denom = __fadd_rn(__fsub_rn(__fadd_rn(ai, aj), inter), 1e-7f);
            sup = (__fdiv_rn(inter, denom) > IOU_T);
        }
        u32 word = __ballot_sync(0xFFFFFFFFu, sup);
        if (lane == 0) gm[i * MASKW + w] = word;
        i++;
    }
}

// ============================================================
// 4) sweep: pipelined resolve/accumulate, 1 barrier per chunk
// ============================================================
#define STEP(b, d) { u32 s = (u32)((int)(alive << (31 - (b))) >> 31); \
                     alive &= ~((d) & s); }

__global__ __launch_bounds__(SWEEP_T, 1)
void k_sweep(const float* __restrict__ pred,
             float* __restrict__ out,
             float* __restrict__ keep_out)
{
    extern __shared__ unsigned char sraw[];
    u32* smask  = (u32*)sraw;                 // 1024*32 (pad rows zeroed)
    u32* sdiag  = smask + 1024 * MASKW;       // 1024 (per-chunk diagonal block)
    u32* ssup   = sdiag + 1024;               // 1024 (chunk w -> word w+1 block)
    u32* svalid = ssup + 1024;                // 32
    u32* skeep  = svalid + 32;                // 32
    u32* sremv  = skeep + 32;                 // 32 (lazily accumulated)

    const int img  = blockIdx.x;
    const int tid  = threadIdx.x;
    const int warp = tid >> 5, lane = tid & 31;

    // mask fill (L2-resident), vectorized; zero pad rows 1000..1023
    {
        const uint4* src = (const uint4*)(g_mask + (size_t)img * TOPK * MASKW);
        uint4* dst = (uint4*)smask;
        for (int k = tid; k < TOPK * MASKW / 4; k += SWEEP_T) dst[k] = src[k];
        for (int k = TOPK * MASKW + tid; k < 1024 * MASKW; k += SWEEP_T) smask[k] = 0;
    }

    // validity ballots
    for (int k = 0; k < 1024; k += SWEEP_T) {
        int t = k + tid;
        float sc = (t < TOPK) ? g_score[img * 1024 + t] : -1.0f;
        u32 vb = __ballot_sync(0xFFFFFFFFu, sc > CONF_T);
        if (lane == 0) svalid[t >> 5] = vb;
    }
    if (tid < 32) sremv[tid] = 0;
    __syncthreads();

    // contiguous diag + superdiag extraction
    for (int t = tid; t < 1024; t += SWEEP_T) {
        int c = t >> 5;
        sdiag[t] = smask[t * 32 + c];
        ssup[t]  = (c + 1 < 32) ? smask[t * 32 + c + 1] : 0u;
    }
    __syncthreads();

    u32 carry = 0;   // warp0-uniform: chunk w-1's suppression into word w
    for (int w = 0; w < 32; w++) {
        if (warp == 0) {
            const uint4* dq = (const uint4*)(sdiag + w * 32);
            uint4 q0 = dq[0], q1 = dq[1], q2 = dq[2], q3 = dq[3];
            uint4 q4 = dq[4], q5 = dq[5], q6 = dq[6], q7 = dq[7];
            u32 alive = svalid[w] & ~(sremv[w] | carry);
            STEP( 0, q0.x) STEP( 1, q0.y) STEP( 2, q0.z) STEP( 3, q0.w)
            STEP( 4, q1.x) STEP( 5, q1.y) STEP( 6, q1.z) STEP( 7, q1.w)
            STEP( 8, q2.x) STEP( 9, q2.y) STEP(10, q2.z) STEP(11, q2.w)
            STEP(12, q3.x) STEP(13, q3.y) STEP(14, q3.z) STEP(15, q3.w)
            STEP(16, q4.x) STEP(17, q4.y) STEP(18, q4.z) STEP(19, q4.w)
            STEP(20, q5.x) STEP(21, q5.y) STEP(22, q5.z) STEP(23, q5.w)
            STEP(24, q6.x) STEP(25, q6.y) STEP(26, q6.z) STEP(27, q6.w)
            STEP(28, q7.x) STEP(29, q7.y) STEP(30, q7.z) STEP(31, q7.w)
            if (lane == 0) skeep[w] = alive;
            u32 contrib = ssup[w * 32 + lane] & (0u - ((alive >> lane) & 1u));
            carry = __reduce_or_sync(0xFFFFFFFFu, contrib);
        } else if (w > 0) {
            u32 a = skeep[w - 1];
            u32 partial = 0;
            for (int b = warp - 1; b < 32; b += 15) {
                if ((a >> b) & 1u)
                    partial |= smask[((w - 1) * 32 + b) * 32 + lane];
            }
            if (partial) atomicOr(&sremv[lane], partial);
        }
        __syncthreads();
    }

    const float* p = pred + (size_t)img * NPRED * PRED_C;
    for (int t = tid; t < TOPK; t += SWEEP_T) {
        bool kp = (skeep[t >> 5] >> (t & 31)) & 1u;
        float o0=0.f,o1=0.f,o2=0.f,o3=0.f,o4=0.f,o6=0.f,o7=0.f,o8=0.f;
        if (kp) {
            float4 b = g_box[img * 1024 + t];
            o0 = b.x; o1 = b.y; o2 = b.z; o3 = b.w;
            o4 = g_score[img * 1024 + t];
            int idx = g_idx[img * 1024 + t];
            o6 = p[idx * PRED_C + 6];
            o7 = p[idx * PRED_C + 7];
            o8 = p[idx * PRED_C + 8];
        }
        float* orow = out + ((size_t)img * TOPK + t) * PRED_C;
        orow[0]=o0; orow[1]=o1; orow[2]=o2; orow[3]=o3;
        orow[4]=o4; orow[5]=0.0f;
        orow[6]=o6; orow[7]=o7; orow[8]=o8;
        keep_out[(size_t)img * TOPK + t] = kp ? 1.0f : 0.0f;
    }
}

extern "C" void kernel_launch(void* const* d_in, const int* in_sizes, int n_in,
                              void* d_out, int out_size)
{
    const float* pred = (const float*)d_in[0];
    int B = in_sizes[0] / (NPRED * PRED_C);

    float* out  = (float*)d_out;
    float* keep = out + (size_t)B * TOPK * PRED_C;

    size_t smemSort  = (size_t)CANDCAP * 8 + (size_t)SEL_N * 8 * 2 +
                       1024 * 4 + 64 * 4 + 80 * 4;
    size_t smemSweep = (size_t)1024 * MASKW * 4 + 2 * 1024 * 4 + 128 * 4;

    static bool attr_set = false;
    if (!attr_set) {
        cudaFuncSetAttribute(k_sort,  cudaFuncAttributeMaxDynamicSharedMemorySize,
                             (int)smemSort);
        cudaFuncSetAttribute(k_sweep, cudaFuncAttributeMaxDynamicSharedMemorySize,
                             (int)smemSweep);
        attr_set = true;
    }

    k_filter<<<dim3(B, NSLICE), FILT_T>>>(pred);
    k_sort<<<B, SORT_T, smemSort>>>(pred);
    k_mask<<<dim3(B, MSLICES), MASK_T>>>();
    k_sweep<<<B, SWEEP_T, smemSweep>>>(pred, out, keep);
}